// round 8
// baseline (speedup 1.0000x reference)
#include <cuda_runtime.h>
#include <cstdint>

#define Bn 128
#define Ln 512
#define En 512
#define Hn 256
#define G4 1024
#define Kn 64

// ---------------- scratch (static device allocations) ----------------
__device__ uint32_t g_preB[2][Ln][Bn][G4/2];   // 268MB: pre-activations bf16x2 [dir][t][b][gate_pair]
__device__ uint32_t g_hN[2][2][Hn/2][Bn];      // h state bf16x2, double-buffered [parity][dir][m_pair][b]
__device__ uint32_t g_histB[Ln][Bn][Hn];       // 67MB: concat hidden states bf16x2 [t][b][h_pair]
__device__ float g_emit[Bn][Ln][Kn];           // emissions [b][t][k]
__device__ unsigned int g_flagv[2][64];        // per-CTA epoch flags (monotonic across replays)
__device__ uint32_t g_xb[Bn][Ln][En/2];        // 67MB: x in bf16x2
__device__ uint32_t g_wihb2[2][G4][En/2];      // W_ih bf16x2 (2MB)
__device__ uint32_t g_wemb[Kn][En/2];          // w_emit bf16x2 (64KB)

__device__ __forceinline__ float sigf(float x) {
    return 1.0f / (1.0f + __expf(-x));
}
__device__ __forceinline__ float tanhfast(float x) {
    float e = __expf(2.0f * x);
    return 1.0f - __fdividef(2.0f, e + 1.0f);
}

__device__ __forceinline__ uint32_t pack_bf16(float lo, float hi) {
    uint32_t r;
    asm("cvt.rn.bf16x2.f32 %0, %1, %2;" : "=r"(r) : "f"(hi), "f"(lo));
    return r;
}
__device__ __forceinline__ float bflo(uint32_t w) { return __uint_as_float(w << 16); }
__device__ __forceinline__ float bfhi(uint32_t w) { return __uint_as_float(w & 0xffff0000u); }

__device__ __forceinline__ void mma_bf16(float* d, const uint32_t* a, const uint32_t* b) {
    asm volatile(
        "mma.sync.aligned.m16n8k16.row.col.f32.bf16.bf16.f32 "
        "{%0,%1,%2,%3}, {%4,%5,%6,%7}, {%8,%9}, {%0,%1,%2,%3};"
        : "+f"(d[0]), "+f"(d[1]), "+f"(d[2]), "+f"(d[3])
        : "r"(a[0]), "r"(a[1]), "r"(a[2]), "r"(a[3]), "r"(b[0]), "r"(b[1]));
}

__device__ __forceinline__ uint4 ld_relaxed_v4(const uint4* p) {
    uint4 v;
    asm volatile("ld.relaxed.gpu.global.v4.u32 {%0,%1,%2,%3}, [%4];"
                 : "=r"(v.x), "=r"(v.y), "=r"(v.z), "=r"(v.w) : "l"(p) : "memory");
    return v;
}

// ---------------- 0) prep: fp32 -> bf16x2 conversions ----------------
__global__ void __launch_bounds__(256) k_cvt_x(const float* __restrict__ x) {
    uint32_t* dst = &g_xb[0][0][0];
    int i = blockIdx.x * 512 + threadIdx.x * 2;     // 2 float4 per thread
#pragma unroll
    for (int j = 0; j < 2; j++) {
        int f = i + j;
        float4 v = *(const float4*)(x + (size_t)f * 4);
        *(uint2*)(dst + (size_t)f * 2) = make_uint2(pack_bf16(v.x, v.y), pack_bf16(v.z, v.w));
    }
}

#define WF4 131072      // 1024*512/4
__global__ void __launch_bounds__(256) k_cvt_w(
    const float* __restrict__ wf, const float* __restrict__ wb,
    const float* __restrict__ wem)
{
    int f = blockIdx.x * 256 + threadIdx.x;          // float4 index
    const float* src;
    uint32_t* dst;
    if (f < WF4)           { src = wf;  dst = &g_wihb2[0][0][0]; }
    else if (f < 2 * WF4)  { src = wb;  dst = &g_wihb2[1][0][0]; f -= WF4; }
    else                   { src = wem; dst = &g_wemb[0][0];     f -= 2 * WF4;
                             if (f >= Kn * En / 4) return; }
    float4 v = *(const float4*)(src + (size_t)f * 4);
    *(uint2*)(dst + (size_t)f * 2) = make_uint2(pack_bf16(v.x, v.y), pack_bf16(v.z, v.w));
}

// ---------------- 1) input GEMM (mma.sync bf16, bf16 operands): pre = x @ W_ih^T + b ----------------
__global__ void __launch_bounds__(256) k_gemm_bf16(
    const float* __restrict__ bihf, const float* __restrict__ bhhf,
    const float* __restrict__ bihb, const float* __restrict__ bhhb)
{
    const int gtile = blockIdx.x;           // 0..7
    const int t     = blockIdx.y;           // 0..511
    const int dir   = blockIdx.z;           // 0,1
    const int t_eff = dir ? (Ln - 1 - t) : t;
    const int g0 = gtile * 128;

    __shared__ uint32_t As[16][136];   // [k2][b]  bf16x2 (x)
    __shared__ uint32_t Bs[16][136];   // [k2][g]  bf16x2 (W)

    const int tid  = threadIdx.x;
    const int wid  = tid >> 5;
    const int lane = tid & 31;
    const int wm   = (wid >> 2) * 64;   // warp M (batch) base
    const int wn   = (wid & 3) * 32;    // warp N (gate) base
    const int grp  = lane >> 2;         // 0..7
    const int qk   = lane & 3;          // 0..3

    float acc[4][4][4];                 // [mi][ni][reg]
#pragma unroll
    for (int mi = 0; mi < 4; mi++)
#pragma unroll
        for (int ni = 0; ni < 4; ni++)
#pragma unroll
            for (int r = 0; r < 4; r++) acc[mi][ni][r] = 0.0f;

    for (int k0w = 0; k0w < En / 2; k0w += 16) {       // 16 words = 32 k per stage
#pragma unroll
        for (int i = 0; i < 2; i++) {
            int idx = (i << 8) + tid;        // 0..511
            int r   = idx >> 2;              // row 0..127
            int q   = idx & 3;               // quad of words
            uint4 va = *(const uint4*)&g_xb[r][t_eff][k0w + q * 4];
            As[q * 4 + 0][r] = va.x; As[q * 4 + 1][r] = va.y;
            As[q * 4 + 2][r] = va.z; As[q * 4 + 3][r] = va.w;
            uint4 vb = *(const uint4*)&g_wihb2[dir][g0 + r][k0w + q * 4];
            Bs[q * 4 + 0][r] = vb.x; Bs[q * 4 + 1][r] = vb.y;
            Bs[q * 4 + 2][r] = vb.z; Bs[q * 4 + 3][r] = vb.w;
        }
        __syncthreads();
#pragma unroll
        for (int kc2 = 0; kc2 < 16; kc2 += 8) {
            uint32_t af[4][4];    // [mi][reg]
            uint32_t bf[4][2];    // [ni][reg]
#pragma unroll
            for (int mi = 0; mi < 4; mi++) {
                int m = wm + mi * 16 + grp;
                af[mi][0] = As[kc2 + qk][m];
                af[mi][1] = As[kc2 + qk][m + 8];
                af[mi][2] = As[kc2 + 4 + qk][m];
                af[mi][3] = As[kc2 + 4 + qk][m + 8];
            }
#pragma unroll
            for (int ni = 0; ni < 4; ni++) {
                int n = wn + ni * 8 + grp;
                bf[ni][0] = Bs[kc2 + qk][n];
                bf[ni][1] = Bs[kc2 + 4 + qk][n];
            }
#pragma unroll
            for (int mi = 0; mi < 4; mi++)
#pragma unroll
                for (int ni = 0; ni < 4; ni++)
                    mma_bf16(acc[mi][ni], af[mi], bf[ni]);
        }
        __syncthreads();
    }

    // epilogue
    const float* __restrict__ bih = dir ? bihb : bihf;
    const float* __restrict__ bhh = dir ? bhhb : bhhf;
#pragma unroll
    for (int ni = 0; ni < 4; ni++) {
        int gate0 = g0 + wn + ni * 8 + 2 * qk;
        float bias0 = bih[gate0] + bhh[gate0];
        float bias1 = bih[gate0 + 1] + bhh[gate0 + 1];
        int g2w = (g0 + wn + ni * 8) / 2 + qk;
#pragma unroll
        for (int mi = 0; mi < 4; mi++) {
            int bA = wm + mi * 16 + grp;
            g_preB[dir][t][bA][g2w]     = pack_bf16(acc[mi][ni][0] + bias0, acc[mi][ni][1] + bias1);
            g_preB[dir][t][bA + 8][g2w] = pack_bf16(acc[mi][ni][2] + bias0, acc[mi][ni][3] + bias1);
        }
    }
}

// ---------------- 2) LSTM recurrence: persistent, gate-sliced, mma bf16, flag barrier v2 ----------------
__global__ void __launch_bounds__(256) k_lstm2(
    const float* __restrict__ whf, const float* __restrict__ whb)
{
    const int dir   = blockIdx.x >> 6;
    const int slice = blockIdx.x & 63;
    const int m0    = slice << 2;
    const float* __restrict__ whh = dir ? whb : whf;

    const int tid  = threadIdx.x;
    const int wid  = tid >> 5;
    const int lane = tid & 31;
    const int grp  = lane >> 2;
    const int qk   = lane & 3;
    const int bm   = wid * 16;          // warp's batch-row base

    const unsigned int ep0 = *(volatile unsigned int*)&g_flagv[dir][slice];

    // ---- B fragments (W_hh slice), persistent in registers ----
    uint32_t B0[2][16], B1[2][16];
#pragma unroll
    for (int nt = 0; nt < 2; nt++) {
        int c = nt * 8 + grp;                         // slice col 0..15
        int gcol = (c >> 2) * 256 + m0 + (c & 3);     // global gate
        const float* wr = whh + (size_t)gcol * Hn;
#pragma unroll
        for (int kb = 0; kb < 16; kb++) {
            float2 w0 = *(const float2*)(wr + kb * 16 + 2 * qk);
            float2 w1 = *(const float2*)(wr + kb * 16 + 8 + 2 * qk);
            B0[nt][kb] = pack_bf16(w0.x, w0.y);
            B1[nt][kb] = pack_bf16(w1.x, w1.y);
        }
    }

    float cst0 = 0.0f, cst1 = 0.0f;                   // cell state (2 per lane)
    const int rb      = (qk >= 2) ? 2 : 0;
    const int b_row   = bm + grp + ((qk >= 2) ? 8 : 0);
    const int m2w     = (m0 >> 1) + (qk & 1);
    const int hwrd    = dir * 128 + (m0 >> 1) + (qk & 1);  // hist word col

    const int wrd0 = ((qk >> 1)) * 128 + m2w;       // nt=0 preB word
    const int wrd1 = (2 + (qk >> 1)) * 128 + m2w;   // nt=1 preB word

    // prefetch preB for t=0
    uint32_t pw[4];
    pw[0] = g_preB[dir][0][bm + grp][wrd0];
    pw[1] = g_preB[dir][0][bm + grp + 8][wrd0];
    pw[2] = g_preB[dir][0][bm + grp][wrd1];
    pw[3] = g_preB[dir][0][bm + grp + 8][wrd1];

    for (int t = 0; t < Ln; t++) {
        float acc[2][4];
#pragma unroll
        for (int nt = 0; nt < 2; nt++)
#pragma unroll
            for (int r = 0; r < 4; r++) acc[nt][r] = 0.0f;

        if (t > 0) {
            const uint32_t* __restrict__ hp = &g_hN[(t & 1) ^ 1][dir][0][0];
            uint32_t ab[4][4];
#define LDA(d, kb) do {                                                   \
                const uint32_t* _r0 = hp + ((kb) * 8 + qk) * Bn;          \
                const uint32_t* _r1 = hp + ((kb) * 8 + 4 + qk) * Bn;      \
                (d)[0] = __ldcg(_r0 + bm + grp);                          \
                (d)[1] = __ldcg(_r0 + bm + grp + 8);                      \
                (d)[2] = __ldcg(_r1 + bm + grp);                          \
                (d)[3] = __ldcg(_r1 + bm + grp + 8);                      \
            } while (0)
            LDA(ab[0], 0); LDA(ab[1], 1); LDA(ab[2], 2); LDA(ab[3], 3);
#pragma unroll
            for (int kb = 0; kb < 16; kb++) {
                uint32_t a[4];
                a[0] = ab[kb & 3][0]; a[1] = ab[kb & 3][1];
                a[2] = ab[kb & 3][2]; a[3] = ab[kb & 3][3];
                if (kb + 4 < 16) LDA(ab[kb & 3], kb + 4);
                uint32_t b0[2] = {B0[0][kb], B1[0][kb]};
                uint32_t b1[2] = {B0[1][kb], B1[1][kb]};
                mma_bf16(acc[0], a, b0);
                mma_bf16(acc[1], a, b1);
            }
#undef LDA
        }

        // add pre-activations (prefetched)
        acc[0][0] += bflo(pw[0]); acc[0][1] += bfhi(pw[0]);
        acc[0][2] += bflo(pw[1]); acc[0][3] += bfhi(pw[1]);
        acc[1][0] += bflo(pw[2]); acc[1][1] += bfhi(pw[2]);
        acc[1][2] += bflo(pw[3]); acc[1][3] += bfhi(pw[3]);

        // exchange with lane^2: (i,g) <-> (f,o)
        float recv[2][4];
#pragma unroll
        for (int nt = 0; nt < 2; nt++)
#pragma unroll
            for (int r = 0; r < 4; r++)
                recv[nt][r] = __shfl_xor_sync(0xffffffffu, acc[nt][r], 2);

        const bool ig = (qk < 2);
        float h0, h1;
        {
            float i_ = ig ? acc[0][rb + 0] : recv[0][rb + 0];
            float f_ = ig ? recv[0][rb + 0] : acc[0][rb + 0];
            float g_ = ig ? acc[1][rb + 0] : recv[1][rb + 0];
            float o_ = ig ? recv[1][rb + 0] : acc[1][rb + 0];
            cst0 = sigf(f_) * cst0 + sigf(i_) * tanhfast(g_);
            h0 = sigf(o_) * tanhfast(cst0);
        }
        {
            float i_ = ig ? acc[0][rb + 1] : recv[0][rb + 1];
            float f_ = ig ? recv[0][rb + 1] : acc[0][rb + 1];
            float g_ = ig ? acc[1][rb + 1] : recv[1][rb + 1];
            float o_ = ig ? recv[1][rb + 1] : acc[1][rb + 1];
            cst1 = sigf(f_) * cst1 + sigf(i_) * tanhfast(g_);
            h1 = sigf(o_) * tanhfast(cst1);
        }

        // publish h: bf16x2 word for next step + bf16x2 history
        uint32_t hw = pack_bf16(h0, h1);
        __stcg(&g_hN[t & 1][dir][m2w][b_row], hw);
        const int rt = dir ? (Ln - 1 - t) : t;
        __stcg(&g_histB[rt][b_row][hwrd], hw);

        if (t != Ln - 1) {
            // prefetch next step's preB before the barrier (no dependency)
            pw[0] = __ldcg(&g_preB[dir][t + 1][bm + grp][wrd0]);
            pw[1] = __ldcg(&g_preB[dir][t + 1][bm + grp + 8][wrd0]);
            pw[2] = __ldcg(&g_preB[dir][t + 1][bm + grp][wrd1]);
            pw[3] = __ldcg(&g_preB[dir][t + 1][bm + grp + 8][wrd1]);
            // barrier v2: distributed flags, one release-store + one poller per CTA
            const unsigned int tgt = ep0 + (unsigned)t + 1u;
            __syncthreads();                 // CTA stores complete before release
            if (tid == 0) {
                asm volatile("st.release.gpu.global.u32 [%0], %1;"
                             :: "l"(&g_flagv[dir][slice]), "r"(tgt) : "memory");
                const uint4* f = (const uint4*)&g_flagv[dir][0];
                while (true) {
                    bool ok = true;
#pragma unroll
                    for (int i = 0; i < 16; i++) {
                        uint4 v = ld_relaxed_v4(f + i);
                        ok = ok && (v.x >= tgt) && (v.y >= tgt)
                                && (v.z >= tgt) && (v.w >= tgt);
                    }
                    if (ok) break;
                    __nanosleep(32);
                }
                asm volatile("fence.acq_rel.gpu;" ::: "memory");
            }
            __syncthreads();
        }
    }
    // keep all flags consistent for the next replay
    __syncthreads();
    if (tid == 0)
        asm volatile("st.release.gpu.global.u32 [%0], %1;"
                     :: "l"(&g_flagv[dir][slice]), "r"(ep0 + (unsigned)Ln) : "memory");
}

// ---------------- 3) emit GEMM (mma bf16): emit[b][t][k] = histB[t][b] @ wemb^T + b_emit ----------------
__global__ void __launch_bounds__(256) k_emit2(const float* __restrict__ bem)
{
    const int t = blockIdx.x;
    __shared__ uint32_t As[32][136];   // [k2][b]
    __shared__ uint32_t Bs[32][72];    // [k2][k-col]

    const int tid  = threadIdx.x;
    const int wid  = tid >> 5;
    const int lane = tid & 31;
    const int grp  = lane >> 2;
    const int qk   = lane & 3;
    const int wm   = wid * 16;          // warp batch base

    float acc[8][4];
#pragma unroll
    for (int nb = 0; nb < 8; nb++)
#pragma unroll
        for (int r = 0; r < 4; r++) acc[nb][r] = 0.0f;

    for (int c = 0; c < 8; c++) {                  // K chunks: 64 h (32 words)
        const int k0w = c * 32;
#pragma unroll
        for (int i = 0; i < 4; i++) {              // A: 128 rows x 32 words
            int idx = (i << 8) + tid;
            int r   = idx >> 3;                    // 0..127
            int q   = idx & 7;
            uint4 v = *(const uint4*)&g_histB[t][r][k0w + q * 4];
            As[q * 4 + 0][r] = v.x; As[q * 4 + 1][r] = v.y;
            As[q * 4 + 2][r] = v.z; As[q * 4 + 3][r] = v.w;
        }
#pragma unroll
        for (int i = 0; i < 2; i++) {              // B: 64 rows x 32 words
            int idx = (i << 8) + tid;
            int r   = idx >> 3;                    // 0..63
            int q   = idx & 7;
            uint4 v = *(const uint4*)&g_wemb[r][k0w + q * 4];
            Bs[q * 4 + 0][r] = v.x; Bs[q * 4 + 1][r] = v.y;
            Bs[q * 4 + 2][r] = v.z; Bs[q * 4 + 3][r] = v.w;
        }
        __syncthreads();
#pragma unroll
        for (int kb = 0; kb < 4; kb++) {
            int k2 = kb * 8;
            uint32_t a[4];
            a[0] = As[k2 + qk][wm + grp];
            a[1] = As[k2 + qk][wm + grp + 8];
            a[2] = As[k2 + 4 + qk][wm + grp];
            a[3] = As[k2 + 4 + qk][wm + grp + 8];
#pragma unroll
            for (int nb = 0; nb < 8; nb++) {
                uint32_t b[2] = {Bs[k2 + qk][nb * 8 + grp], Bs[k2 + 4 + qk][nb * 8 + grp]};
                mma_bf16(acc[nb], a, b);
            }
        }
        __syncthreads();
    }

#pragma unroll
    for (int nb = 0; nb < 8; nb++) {
        int k = nb * 8 + qk * 2;
        float b0 = bem[k], b1 = bem[k + 1];
        *(float2*)&g_emit[wm + grp][t][k]     = make_float2(acc[nb][0] + b0, acc[nb][1] + b1);
        *(float2*)&g_emit[wm + grp + 8][t][k] = make_float2(acc[nb][2] + b0, acc[nb][3] + b1);
    }
}

// ---------------- 4) CRF forward + gold score: warp per batch, reduction-free shift ----------------
__global__ void __launch_bounds__(32) k_crf(
    const int* __restrict__ labels,
    const float* __restrict__ trans,
    float* __restrict__ out)
{
    const int b = blockIdx.x;
    const int lane = threadIdx.x;
    __shared__ float ps[64];

    float eTc0[64], eTc1[64];
#pragma unroll 8
    for (int i = 0; i < 64; i++) {
        eTc0[i] = __expf(trans[i * 64 + lane]);
        eTc1[i] = __expf(trans[i * 64 + lane + 32]);
    }

    float d0 = g_emit[b][0][lane];
    float d1 = g_emit[b][0][lane + 32];
    float Cacc = 0.0f, Ckah = 0.0f;

    for (int t = 1; t < Ln; t++) {
        float c = __shfl_sync(0xffffffffu, d0, 0);
        ps[lane]      = __expf(d0 - c);
        ps[lane + 32] = __expf(d1 - c);
        __syncwarp();
        float s0a = 0.f, s0b = 0.f, s1a = 0.f, s1b = 0.f;
#pragma unroll
        for (int i = 0; i < 64; i += 2) {
            float pi = ps[i], pj = ps[i + 1];
            s0a = fmaf(pi, eTc0[i], s0a);
            s0b = fmaf(pj, eTc0[i + 1], s0b);
            s1a = fmaf(pi, eTc1[i], s1a);
            s1b = fmaf(pj, eTc1[i + 1], s1b);
        }
        d0 = g_emit[b][t][lane]      + __logf(s0a + s0b);
        d1 = g_emit[b][t][lane + 32] + __logf(s1a + s1b);
        float y = c - Ckah;
        float tt = Cacc + y;
        Ckah = (tt - Cacc) - y;
        Cacc = tt;
        __syncwarp();
    }

    float m = fmaxf(d0, d1);
#pragma unroll
    for (int o = 16; o > 0; o >>= 1)
        m = fmaxf(m, __shfl_xor_sync(0xffffffffu, m, o));
    float sp = __expf(d0 - m) + __expf(d1 - m);
#pragma unroll
    for (int o = 16; o > 0; o >>= 1)
        sp += __shfl_xor_sync(0xffffffffu, sp, o);
    float logz = m + __logf(sp) + Cacc;

    float gold = 0.0f;
    for (int t = lane; t < Ln; t += 32) {
        int lab = labels[b * Ln + t];
        gold += g_emit[b][t][lab];
        if (t < Ln - 1) {
            int lab2 = labels[b * Ln + t + 1];
            gold += trans[lab * 64 + lab2];
        }
    }
#pragma unroll
    for (int o = 16; o > 0; o >>= 1)
        gold += __shfl_xor_sync(0xffffffffu, gold, o);

    if (lane == 0) out[b] = logz - gold;
}

// ---------------- launch ----------------
extern "C" void kernel_launch(void* const* d_in, const int* in_sizes, int n_in,
                              void* d_out, int out_size)
{
    const float* x     = (const float*)d_in[0];
    const int*   lab   = (const int*)d_in[1];
    const float* wihf  = (const float*)d_in[2];
    const float* whhf  = (const float*)d_in[3];
    const float* bihf  = (const float*)d_in[4];
    const float* bhhf  = (const float*)d_in[5];
    const float* wihb  = (const float*)d_in[6];
    const float* whhb  = (const float*)d_in[7];
    const float* bihb  = (const float*)d_in[8];
    const float* bhhb  = (const float*)d_in[9];
    const float* wem   = (const float*)d_in[10];
    const float* bem   = (const float*)d_in[11];
    const float* trans = (const float*)d_in[12];
    float* out = (float*)d_out;

    k_cvt_x<<<16384, 256>>>(x);
    k_cvt_w<<<1088, 256>>>(wihf, wihb, wem);
    dim3 gg(8, 512, 2);
    k_gemm_bf16<<<gg, 256>>>(bihf, bhhf, bihb, bhhb);
    k_lstm2<<<128, 256>>>(whhf, whhb);
    k_emit2<<<512, 256>>>(bem);
    k_crf<<<128, 32>>>(lab, trans, out);
}

// round 9
// speedup vs baseline: 2.6901x; 2.6901x over previous
#include <cuda_runtime.h>
#include <cstdint>

#define Bn 128
#define Ln 512
#define En 512
#define Hn 256
#define G4 1024
#define Kn 64

// ---------------- scratch (static device allocations) ----------------
__device__ uint32_t g_preB[2][Ln][Bn][G4/2];   // 268MB: pre-activations bf16x2 [dir][t][b][gate_pair]
__device__ uint32_t g_hN[2][2][Hn/2][Bn];      // h state bf16x2, double-buffered [parity][dir][m_pair][b]
__device__ uint32_t g_histB[Ln][Bn][Hn];       // 67MB: concat hidden states bf16x2 [t][b][h_pair]
__device__ float g_emit[Bn][Ln][Kn];           // emissions [b][t][k]
__device__ unsigned long long g_bar[32];       // spin-barrier counters (monotonic across replays)
__device__ uint32_t g_xb[Bn][Ln][En/2];        // 67MB: x in bf16x2
__device__ uint32_t g_wihb2[2][G4][En/2];      // W_ih bf16x2 (2MB)
__device__ uint32_t g_wemb[Kn][En/2];          // w_emit bf16x2 (64KB)

__device__ __forceinline__ float sigf(float x) {
    return 1.0f / (1.0f + __expf(-x));
}
__device__ __forceinline__ float tanhfast(float x) {
    float e = __expf(2.0f * x);
    return 1.0f - __fdividef(2.0f, e + 1.0f);
}

__device__ __forceinline__ uint32_t pack_bf16(float lo, float hi) {
    uint32_t r;
    asm("cvt.rn.bf16x2.f32 %0, %1, %2;" : "=r"(r) : "f"(hi), "f"(lo));
    return r;
}
__device__ __forceinline__ float bflo(uint32_t w) { return __uint_as_float(w << 16); }
__device__ __forceinline__ float bfhi(uint32_t w) { return __uint_as_float(w & 0xffff0000u); }

__device__ __forceinline__ void mma_bf16(float* d, const uint32_t* a, const uint32_t* b) {
    asm volatile(
        "mma.sync.aligned.m16n8k16.row.col.f32.bf16.bf16.f32 "
        "{%0,%1,%2,%3}, {%4,%5,%6,%7}, {%8,%9}, {%0,%1,%2,%3};"
        : "+f"(d[0]), "+f"(d[1]), "+f"(d[2]), "+f"(d[3])
        : "r"(a[0]), "r"(a[1]), "r"(a[2]), "r"(a[3]), "r"(b[0]), "r"(b[1]));
}

// ---------------- 0) prep: fp32 -> bf16x2 conversions ----------------
__global__ void __launch_bounds__(256) k_cvt_x(const float* __restrict__ x) {
    uint32_t* dst = &g_xb[0][0][0];
    int i = blockIdx.x * 512 + threadIdx.x * 2;     // 2 float4 per thread
#pragma unroll
    for (int j = 0; j < 2; j++) {
        int f = i + j;
        float4 v = *(const float4*)(x + (size_t)f * 4);
        *(uint2*)(dst + (size_t)f * 2) = make_uint2(pack_bf16(v.x, v.y), pack_bf16(v.z, v.w));
    }
}

#define WF4 131072      // 1024*512/4
__global__ void __launch_bounds__(256) k_cvt_w(
    const float* __restrict__ wf, const float* __restrict__ wb,
    const float* __restrict__ wem)
{
    int f = blockIdx.x * 256 + threadIdx.x;          // float4 index
    const float* src;
    uint32_t* dst;
    if (f < WF4)           { src = wf;  dst = &g_wihb2[0][0][0]; }
    else if (f < 2 * WF4)  { src = wb;  dst = &g_wihb2[1][0][0]; f -= WF4; }
    else                   { src = wem; dst = &g_wemb[0][0];     f -= 2 * WF4;
                             if (f >= Kn * En / 4) return; }
    float4 v = *(const float4*)(src + (size_t)f * 4);
    *(uint2*)(dst + (size_t)f * 2) = make_uint2(pack_bf16(v.x, v.y), pack_bf16(v.z, v.w));
}

// ---------------- 1) input GEMM (mma.sync bf16, bf16 operands): pre = x @ W_ih^T + b ----------------
__global__ void __launch_bounds__(256) k_gemm_bf16(
    const float* __restrict__ bihf, const float* __restrict__ bhhf,
    const float* __restrict__ bihb, const float* __restrict__ bhhb)
{
    const int gtile = blockIdx.x;           // 0..7
    const int t     = blockIdx.y;           // 0..511
    const int dir   = blockIdx.z;           // 0,1
    const int t_eff = dir ? (Ln - 1 - t) : t;
    const int g0 = gtile * 128;

    __shared__ uint32_t As[16][136];   // [k2][b]  bf16x2 (x)
    __shared__ uint32_t Bs[16][136];   // [k2][g]  bf16x2 (W)

    const int tid  = threadIdx.x;
    const int wid  = tid >> 5;
    const int lane = tid & 31;
    const int wm   = (wid >> 2) * 64;   // warp M (batch) base
    const int wn   = (wid & 3) * 32;    // warp N (gate) base
    const int grp  = lane >> 2;         // 0..7
    const int qk   = lane & 3;          // 0..3

    float acc[4][4][4];                 // [mi][ni][reg]
#pragma unroll
    for (int mi = 0; mi < 4; mi++)
#pragma unroll
        for (int ni = 0; ni < 4; ni++)
#pragma unroll
            for (int r = 0; r < 4; r++) acc[mi][ni][r] = 0.0f;

    for (int k0w = 0; k0w < En / 2; k0w += 16) {       // 16 words = 32 k per stage
#pragma unroll
        for (int i = 0; i < 2; i++) {
            int idx = (i << 8) + tid;        // 0..511
            int r   = idx >> 2;              // row 0..127
            int q   = idx & 3;               // quad of words
            uint4 va = *(const uint4*)&g_xb[r][t_eff][k0w + q * 4];
            As[q * 4 + 0][r] = va.x; As[q * 4 + 1][r] = va.y;
            As[q * 4 + 2][r] = va.z; As[q * 4 + 3][r] = va.w;
            uint4 vb = *(const uint4*)&g_wihb2[dir][g0 + r][k0w + q * 4];
            Bs[q * 4 + 0][r] = vb.x; Bs[q * 4 + 1][r] = vb.y;
            Bs[q * 4 + 2][r] = vb.z; Bs[q * 4 + 3][r] = vb.w;
        }
        __syncthreads();
#pragma unroll
        for (int kc2 = 0; kc2 < 16; kc2 += 8) {
            uint32_t af[4][4];    // [mi][reg]
            uint32_t bf[4][2];    // [ni][reg]
#pragma unroll
            for (int mi = 0; mi < 4; mi++) {
                int m = wm + mi * 16 + grp;
                af[mi][0] = As[kc2 + qk][m];
                af[mi][1] = As[kc2 + qk][m + 8];
                af[mi][2] = As[kc2 + 4 + qk][m];
                af[mi][3] = As[kc2 + 4 + qk][m + 8];
            }
#pragma unroll
            for (int ni = 0; ni < 4; ni++) {
                int n = wn + ni * 8 + grp;
                bf[ni][0] = Bs[kc2 + qk][n];
                bf[ni][1] = Bs[kc2 + 4 + qk][n];
            }
#pragma unroll
            for (int mi = 0; mi < 4; mi++)
#pragma unroll
                for (int ni = 0; ni < 4; ni++)
                    mma_bf16(acc[mi][ni], af[mi], bf[ni]);
        }
        __syncthreads();
    }

    // epilogue
    const float* __restrict__ bih = dir ? bihb : bihf;
    const float* __restrict__ bhh = dir ? bhhb : bhhf;
#pragma unroll
    for (int ni = 0; ni < 4; ni++) {
        int gate0 = g0 + wn + ni * 8 + 2 * qk;
        float bias0 = bih[gate0] + bhh[gate0];
        float bias1 = bih[gate0 + 1] + bhh[gate0 + 1];
        int g2w = (g0 + wn + ni * 8) / 2 + qk;
#pragma unroll
        for (int mi = 0; mi < 4; mi++) {
            int bA = wm + mi * 16 + grp;
            g_preB[dir][t][bA][g2w]     = pack_bf16(acc[mi][ni][0] + bias0, acc[mi][ni][1] + bias1);
            g_preB[dir][t][bA + 8][g2w] = pack_bf16(acc[mi][ni][2] + bias0, acc[mi][ni][3] + bias1);
        }
    }
}

// ---------------- 2) LSTM recurrence: persistent, gate-sliced, mma bf16, smem-staged h ----------------
__global__ void __launch_bounds__(256) k_lstm2(
    const float* __restrict__ whf, const float* __restrict__ whb)
{
    const int dir   = blockIdx.x >> 6;
    const int slice = blockIdx.x & 63;
    const int m0    = slice << 2;
    const float* __restrict__ whh = dir ? whb : whf;

    const int tid  = threadIdx.x;
    const int wid  = tid >> 5;
    const int lane = tid & 31;
    const int grp  = lane >> 2;
    const int qk   = lane & 3;
    const int bm   = wid * 16;          // warp's batch-row base

    // h staging: 64 rows (one half of the 128 m2-rows) x 128 b-words, stride 136 (conflict-free)
    __shared__ uint32_t hsm[64 * 136];  // 34.8 KB

    // ---- B fragments (W_hh slice), persistent in registers ----
    uint32_t B0[2][16], B1[2][16];
#pragma unroll
    for (int nt = 0; nt < 2; nt++) {
        int c = nt * 8 + grp;                         // slice col 0..15
        int gcol = (c >> 2) * 256 + m0 + (c & 3);     // global gate
        const float* wr = whh + (size_t)gcol * Hn;
#pragma unroll
        for (int kb = 0; kb < 16; kb++) {
            float2 w0 = *(const float2*)(wr + kb * 16 + 2 * qk);
            float2 w1 = *(const float2*)(wr + kb * 16 + 8 + 2 * qk);
            B0[nt][kb] = pack_bf16(w0.x, w0.y);
            B1[nt][kb] = pack_bf16(w1.x, w1.y);
        }
    }

    float cst0 = 0.0f, cst1 = 0.0f;                   // cell state (2 per lane)
    const int rb      = (qk >= 2) ? 2 : 0;
    const int b_row   = bm + grp + ((qk >= 2) ? 8 : 0);
    const int m2w     = (m0 >> 1) + (qk & 1);
    const int hwrd    = dir * 128 + (m0 >> 1) + (qk & 1);  // hist word col
    unsigned long long* const barp = &g_bar[dir * 8];

    const int wrd0 = ((qk >> 1)) * 128 + m2w;       // nt=0 preB word
    const int wrd1 = (2 + (qk >> 1)) * 128 + m2w;   // nt=1 preB word

    // prefetch preB for t=0
    uint32_t pw[4];
    pw[0] = g_preB[dir][0][bm + grp][wrd0];
    pw[1] = g_preB[dir][0][bm + grp + 8][wrd0];
    pw[2] = g_preB[dir][0][bm + grp][wrd1];
    pw[3] = g_preB[dir][0][bm + grp + 8][wrd1];

    // per-thread staging coords (uint4 index within a 2048-uint4 half)
    const int sr0 = tid >> 5;           // base row of this thread's uint4 slots (per i: +8)
    const int sc0 = (tid & 31) * 4;     // word col

    for (int t = 0; t < Ln; t++) {
        float acc[2][4];
#pragma unroll
        for (int nt = 0; nt < 2; nt++)
#pragma unroll
            for (int r = 0; r < 4; r++) acc[nt][r] = 0.0f;

        if (t > 0) {
            const uint4* __restrict__ hp4 =
                (const uint4*)&g_hN[(t & 1) ^ 1][dir][0][0];
            // burst-load both halves (half2 kept in regs during phase-1 mma)
            uint4 st1[8], st2[8];
#pragma unroll
            for (int i = 0; i < 8; i++) st1[i] = __ldcg(hp4 + i * 256 + tid);
#pragma unroll
            for (int i = 0; i < 8; i++) st2[i] = __ldcg(hp4 + 2048 + i * 256 + tid);
            // stage half 1 (rows 0..63)
#pragma unroll
            for (int i = 0; i < 8; i++)
                *(uint4*)&hsm[(sr0 + i * 8) * 136 + sc0] = st1[i];
            __syncthreads();
            // phase 1: kb 0..7
#pragma unroll
            for (int kb = 0; kb < 8; kb++) {
                uint32_t a[4];
                const int r0 = kb * 8 + qk;
                a[0] = hsm[r0 * 136 + bm + grp];
                a[1] = hsm[r0 * 136 + bm + grp + 8];
                a[2] = hsm[(r0 + 4) * 136 + bm + grp];
                a[3] = hsm[(r0 + 4) * 136 + bm + grp + 8];
                uint32_t b0[2] = {B0[0][kb], B1[0][kb]};
                uint32_t b1[2] = {B0[1][kb], B1[1][kb]};
                mma_bf16(acc[0], a, b0);
                mma_bf16(acc[1], a, b1);
            }
            __syncthreads();
            // stage half 2 (rows 64..127 -> hsm rows 0..63)
#pragma unroll
            for (int i = 0; i < 8; i++)
                *(uint4*)&hsm[(sr0 + i * 8) * 136 + sc0] = st2[i];
            __syncthreads();
            // phase 2: kb 8..15
#pragma unroll
            for (int kb = 8; kb < 16; kb++) {
                uint32_t a[4];
                const int r0 = (kb - 8) * 8 + qk;
                a[0] = hsm[r0 * 136 + bm + grp];
                a[1] = hsm[r0 * 136 + bm + grp + 8];
                a[2] = hsm[(r0 + 4) * 136 + bm + grp];
                a[3] = hsm[(r0 + 4) * 136 + bm + grp + 8];
                uint32_t b0[2] = {B0[0][kb], B1[0][kb]};
                uint32_t b1[2] = {B0[1][kb], B1[1][kb]};
                mma_bf16(acc[0], a, b0);
                mma_bf16(acc[1], a, b1);
            }
        }

        // add pre-activations (prefetched)
        acc[0][0] += bflo(pw[0]); acc[0][1] += bfhi(pw[0]);
        acc[0][2] += bflo(pw[1]); acc[0][3] += bfhi(pw[1]);
        acc[1][0] += bflo(pw[2]); acc[1][1] += bfhi(pw[2]);
        acc[1][2] += bflo(pw[3]); acc[1][3] += bfhi(pw[3]);

        // exchange with lane^2: (i,g) <-> (f,o)
        float recv[2][4];
#pragma unroll
        for (int nt = 0; nt < 2; nt++)
#pragma unroll
            for (int r = 0; r < 4; r++)
                recv[nt][r] = __shfl_xor_sync(0xffffffffu, acc[nt][r], 2);

        const bool ig = (qk < 2);
        float h0, h1;
        {
            float i_ = ig ? acc[0][rb + 0] : recv[0][rb + 0];
            float f_ = ig ? recv[0][rb + 0] : acc[0][rb + 0];
            float g_ = ig ? acc[1][rb + 0] : recv[1][rb + 0];
            float o_ = ig ? recv[1][rb + 0] : acc[1][rb + 0];
            cst0 = sigf(f_) * cst0 + sigf(i_) * tanhfast(g_);
            h0 = sigf(o_) * tanhfast(cst0);
        }
        {
            float i_ = ig ? acc[0][rb + 1] : recv[0][rb + 1];
            float f_ = ig ? recv[0][rb + 1] : acc[0][rb + 1];
            float g_ = ig ? acc[1][rb + 1] : recv[1][rb + 1];
            float o_ = ig ? recv[1][rb + 1] : acc[1][rb + 1];
            cst1 = sigf(f_) * cst1 + sigf(i_) * tanhfast(g_);
            h1 = sigf(o_) * tanhfast(cst1);
        }

        // publish h: bf16x2 word for next step + bf16x2 history
        uint32_t hw = pack_bf16(h0, h1);
        __stcg(&g_hN[t & 1][dir][m2w][b_row], hw);
        const int rt = dir ? (Ln - 1 - t) : t;
        __stcg(&g_histB[rt][b_row][hwrd], hw);

        if (t != Ln - 1) {
            // prefetch next step's preB before the barrier (no dependency)
            pw[0] = __ldcg(&g_preB[dir][t + 1][bm + grp][wrd0]);
            pw[1] = __ldcg(&g_preB[dir][t + 1][bm + grp + 8][wrd0]);
            pw[2] = __ldcg(&g_preB[dir][t + 1][bm + grp][wrd1]);
            pw[3] = __ldcg(&g_preB[dir][t + 1][bm + grp + 8][wrd1]);
            // CG-style barrier: syncthreads -> tid0 release-add -> tid0 acquire-poll -> syncthreads
            __syncthreads();
            if (tid == 0) {
                unsigned long long v;
                asm volatile("atom.add.release.gpu.u64 %0, [%1], 1;"
                             : "=l"(v) : "l"(barp) : "memory");
                unsigned long long target = ((v >> 6) + 1ULL) << 6;   // 64 CTAs per direction
                unsigned long long cur;
                while (true) {
                    asm volatile("ld.acquire.gpu.u64 %0, [%1];"
                                 : "=l"(cur) : "l"(barp) : "memory");
                    if (cur >= target) break;
                    __nanosleep(32);
                }
            }
            __syncthreads();
        }
    }
}

// ---------------- 3) emit GEMM (mma bf16): emit[b][t][k] = histB[t][b] @ wemb^T + b_emit ----------------
__global__ void __launch_bounds__(256) k_emit2(const float* __restrict__ bem)
{
    const int t = blockIdx.x;
    __shared__ uint32_t As[32][136];   // [k2][b]
    __shared__ uint32_t Bs[32][72];    // [k2][k-col]

    const int tid  = threadIdx.x;
    const int wid  = tid >> 5;
    const int lane = tid & 31;
    const int grp  = lane >> 2;
    const int qk   = lane & 3;
    const int wm   = wid * 16;          // warp batch base

    float acc[8][4];
#pragma unroll
    for (int nb = 0; nb < 8; nb++)
#pragma unroll
        for (int r = 0; r < 4; r++) acc[nb][r] = 0.0f;

    for (int c = 0; c < 8; c++) {                  // K chunks: 64 h (32 words)
        const int k0w = c * 32;
#pragma unroll
        for (int i = 0; i < 4; i++) {              // A: 128 rows x 32 words
            int idx = (i << 8) + tid;
            int r   = idx >> 3;                    // 0..127
            int q   = idx & 7;
            uint4 v = *(const uint4*)&g_histB[t][r][k0w + q * 4];
            As[q * 4 + 0][r] = v.x; As[q * 4 + 1][r] = v.y;
            As[q * 4 + 2][r] = v.z; As[q * 4 + 3][r] = v.w;
        }
#pragma unroll
        for (int i = 0; i < 2; i++) {              // B: 64 rows x 32 words
            int idx = (i << 8) + tid;
            int r   = idx >> 3;                    // 0..63
            int q   = idx & 7;
            uint4 v = *(const uint4*)&g_wemb[r][k0w + q * 4];
            Bs[q * 4 + 0][r] = v.x; Bs[q * 4 + 1][r] = v.y;
            Bs[q * 4 + 2][r] = v.z; Bs[q * 4 + 3][r] = v.w;
        }
        __syncthreads();
#pragma unroll
        for (int kb = 0; kb < 4; kb++) {
            int k2 = kb * 8;
            uint32_t a[4];
            a[0] = As[k2 + qk][wm + grp];
            a[1] = As[k2 + qk][wm + grp + 8];
            a[2] = As[k2 + 4 + qk][wm + grp];
            a[3] = As[k2 + 4 + qk][wm + grp + 8];
#pragma unroll
            for (int nb = 0; nb < 8; nb++) {
                uint32_t b[2] = {Bs[k2 + qk][nb * 8 + grp], Bs[k2 + 4 + qk][nb * 8 + grp]};
                mma_bf16(acc[nb], a, b);
            }
        }
        __syncthreads();
    }

#pragma unroll
    for (int nb = 0; nb < 8; nb++) {
        int k = nb * 8 + qk * 2;
        float b0 = bem[k], b1 = bem[k + 1];
        *(float2*)&g_emit[wm + grp][t][k]     = make_float2(acc[nb][0] + b0, acc[nb][1] + b1);
        *(float2*)&g_emit[wm + grp + 8][t][k] = make_float2(acc[nb][2] + b0, acc[nb][3] + b1);
    }
}

// ---------------- 4) CRF forward + gold score: warp per batch, reduction-free shift ----------------
__global__ void __launch_bounds__(32) k_crf(
    const int* __restrict__ labels,
    const float* __restrict__ trans,
    float* __restrict__ out)
{
    const int b = blockIdx.x;
    const int lane = threadIdx.x;
    __shared__ float ps[64];

    float eTc0[64], eTc1[64];
#pragma unroll 8
    for (int i = 0; i < 64; i++) {
        eTc0[i] = __expf(trans[i * 64 + lane]);
        eTc1[i] = __expf(trans[i * 64 + lane + 32]);
    }

    float d0 = g_emit[b][0][lane];
    float d1 = g_emit[b][0][lane + 32];
    float Cacc = 0.0f, Ckah = 0.0f;

    for (int t = 1; t < Ln; t++) {
        float c = __shfl_sync(0xffffffffu, d0, 0);
        ps[lane]      = __expf(d0 - c);
        ps[lane + 32] = __expf(d1 - c);
        __syncwarp();
        float s0a = 0.f, s0b = 0.f, s1a = 0.f, s1b = 0.f;
#pragma unroll
        for (int i = 0; i < 64; i += 2) {
            float pi = ps[i], pj = ps[i + 1];
            s0a = fmaf(pi, eTc0[i], s0a);
            s0b = fmaf(pj, eTc0[i + 1], s0b);
            s1a = fmaf(pi, eTc1[i], s1a);
            s1b = fmaf(pj, eTc1[i + 1], s1b);
        }
        d0 = g_emit[b][t][lane]      + __logf(s0a + s0b);
        d1 = g_emit[b][t][lane + 32] + __logf(s1a + s1b);
        float y = c - Ckah;
        float tt = Cacc + y;
        Ckah = (tt - Cacc) - y;
        Cacc = tt;
        __syncwarp();
    }

    float m = fmaxf(d0, d1);
#pragma unroll
    for (int o = 16; o > 0; o >>= 1)
        m = fmaxf(m, __shfl_xor_sync(0xffffffffu, m, o));
    float sp = __expf(d0 - m) + __expf(d1 - m);
#pragma unroll
    for (int o = 16; o > 0; o >>= 1)
        sp += __shfl_xor_sync(0xffffffffu, sp, o);
    float logz = m + __logf(sp) + Cacc;

    float gold = 0.0f;
    for (int t = lane; t < Ln; t += 32) {
        int lab = labels[b * Ln + t];
        gold += g_emit[b][t][lab];
        if (t < Ln - 1) {
            int lab2 = labels[b * Ln + t + 1];
            gold += trans[lab * 64 + lab2];
        }
    }
#pragma unroll
    for (int o = 16; o > 0; o >>= 1)
        gold += __shfl_xor_sync(0xffffffffu, gold, o);

    if (lane == 0) out[b] = logz - gold;
}

// ---------------- launch ----------------
extern "C" void kernel_launch(void* const* d_in, const int* in_sizes, int n_in,
                              void* d_out, int out_size)
{
    const float* x     = (const float*)d_in[0];
    const int*   lab   = (const int*)d_in[1];
    const float* wihf  = (const float*)d_in[2];
    const float* whhf  = (const float*)d_in[3];
    const float* bihf  = (const float*)d_in[4];
    const float* bhhf  = (const float*)d_in[5];
    const float* wihb  = (const float*)d_in[6];
    const float* whhb  = (const float*)d_in[7];
    const float* bihb  = (const float*)d_in[8];
    const float* bhhb  = (const float*)d_in[9];
    const float* wem   = (const float*)d_in[10];
    const float* bem   = (const float*)d_in[11];
    const float* trans = (const float*)d_in[12];
    float* out = (float*)d_out;

    k_cvt_x<<<16384, 256>>>(x);
    k_cvt_w<<<1088, 256>>>(wihf, wihb, wem);
    dim3 gg(8, 512, 2);
    k_gemm_bf16<<<gg, 256>>>(bihf, bhhf, bihb, bhhb);
    k_lstm2<<<128, 256>>>(whhf, whhb);
    k_emit2<<<512, 256>>>(bem);
    k_crf<<<128, 32>>>(lab, trans, out);
}

// round 10
// speedup vs baseline: 2.8877x; 1.0734x over previous
#include <cuda_runtime.h>
#include <cstdint>

#define Bn 128
#define Ln 512
#define En 512
#define Hn 256
#define G4 1024
#define Kn 64

// ---------------- scratch (static device allocations) ----------------
__device__ uint32_t g_preB[2][Ln][Bn][G4/2];   // 268MB: pre-activations bf16x2 [dir][t][b][gate_pair]
__device__ uint32_t g_hN[2][2][Hn/2][Bn];      // h state bf16x2, double-buffered [parity][dir][m_pair][b]
__device__ uint32_t g_histB[Ln][Bn][Hn];       // 67MB: concat hidden states bf16x2 [t][b][h_pair]
__device__ float g_emit[Bn][Ln][Kn];           // emissions [b][t][k]
__device__ unsigned long long g_bar[128];      // 16 barrier counters, one per 64B line (monotonic)
__device__ uint32_t g_xb[Bn][Ln][En/2];        // 67MB: x in bf16x2
__device__ uint32_t g_wihb2[2][G4][En/2];      // W_ih bf16x2 (2MB)
__device__ uint32_t g_wemb[Kn][En/2];          // w_emit bf16x2 (64KB)

__device__ __forceinline__ float sigf(float x) {
    return 1.0f / (1.0f + __expf(-x));
}
__device__ __forceinline__ float tanhfast(float x) {
    float e = __expf(2.0f * x);
    return 1.0f - __fdividef(2.0f, e + 1.0f);
}

__device__ __forceinline__ uint32_t pack_bf16(float lo, float hi) {
    uint32_t r;
    asm("cvt.rn.bf16x2.f32 %0, %1, %2;" : "=r"(r) : "f"(hi), "f"(lo));
    return r;
}
__device__ __forceinline__ float bflo(uint32_t w) { return __uint_as_float(w << 16); }
__device__ __forceinline__ float bfhi(uint32_t w) { return __uint_as_float(w & 0xffff0000u); }

__device__ __forceinline__ void mma_bf16(float* d, const uint32_t* a, const uint32_t* b) {
    asm volatile(
        "mma.sync.aligned.m16n8k16.row.col.f32.bf16.bf16.f32 "
        "{%0,%1,%2,%3}, {%4,%5,%6,%7}, {%8,%9}, {%0,%1,%2,%3};"
        : "+f"(d[0]), "+f"(d[1]), "+f"(d[2]), "+f"(d[3])
        : "r"(a[0]), "r"(a[1]), "r"(a[2]), "r"(a[3]), "r"(b[0]), "r"(b[1]));
}

// ---------------- 0) prep: fp32 -> bf16x2 conversions ----------------
__global__ void __launch_bounds__(256) k_cvt_x(const float* __restrict__ x) {
    uint32_t* dst = &g_xb[0][0][0];
    int i = blockIdx.x * 512 + threadIdx.x * 2;     // 2 float4 per thread
#pragma unroll
    for (int j = 0; j < 2; j++) {
        int f = i + j;
        float4 v = *(const float4*)(x + (size_t)f * 4);
        *(uint2*)(dst + (size_t)f * 2) = make_uint2(pack_bf16(v.x, v.y), pack_bf16(v.z, v.w));
    }
}

#define WF4 131072      // 1024*512/4
__global__ void __launch_bounds__(256) k_cvt_w(
    const float* __restrict__ wf, const float* __restrict__ wb,
    const float* __restrict__ wem)
{
    int f = blockIdx.x * 256 + threadIdx.x;          // float4 index
    const float* src;
    uint32_t* dst;
    if (f < WF4)           { src = wf;  dst = &g_wihb2[0][0][0]; }
    else if (f < 2 * WF4)  { src = wb;  dst = &g_wihb2[1][0][0]; f -= WF4; }
    else                   { src = wem; dst = &g_wemb[0][0];     f -= 2 * WF4;
                             if (f >= Kn * En / 4) return; }
    float4 v = *(const float4*)(src + (size_t)f * 4);
    *(uint2*)(dst + (size_t)f * 2) = make_uint2(pack_bf16(v.x, v.y), pack_bf16(v.z, v.w));
}

// ---------------- 1) input GEMM (mma.sync bf16, bf16 operands): pre = x @ W_ih^T + b ----------------
__global__ void __launch_bounds__(256) k_gemm_bf16(
    const float* __restrict__ bihf, const float* __restrict__ bhhf,
    const float* __restrict__ bihb, const float* __restrict__ bhhb)
{
    const int gtile = blockIdx.x;           // 0..7
    const int t     = blockIdx.y;           // 0..511
    const int dir   = blockIdx.z;           // 0,1
    const int t_eff = dir ? (Ln - 1 - t) : t;
    const int g0 = gtile * 128;

    __shared__ uint32_t As[16][136];   // [k2][b]  bf16x2 (x)
    __shared__ uint32_t Bs[16][136];   // [k2][g]  bf16x2 (W)

    const int tid  = threadIdx.x;
    const int wid  = tid >> 5;
    const int lane = tid & 31;
    const int wm   = (wid >> 2) * 64;   // warp M (batch) base
    const int wn   = (wid & 3) * 32;    // warp N (gate) base
    const int grp  = lane >> 2;         // 0..7
    const int qk   = lane & 3;          // 0..3

    float acc[4][4][4];                 // [mi][ni][reg]
#pragma unroll
    for (int mi = 0; mi < 4; mi++)
#pragma unroll
        for (int ni = 0; ni < 4; ni++)
#pragma unroll
            for (int r = 0; r < 4; r++) acc[mi][ni][r] = 0.0f;

    for (int k0w = 0; k0w < En / 2; k0w += 16) {       // 16 words = 32 k per stage
#pragma unroll
        for (int i = 0; i < 2; i++) {
            int idx = (i << 8) + tid;        // 0..511
            int r   = idx >> 2;              // row 0..127
            int q   = idx & 3;               // quad of words
            uint4 va = *(const uint4*)&g_xb[r][t_eff][k0w + q * 4];
            As[q * 4 + 0][r] = va.x; As[q * 4 + 1][r] = va.y;
            As[q * 4 + 2][r] = va.z; As[q * 4 + 3][r] = va.w;
            uint4 vb = *(const uint4*)&g_wihb2[dir][g0 + r][k0w + q * 4];
            Bs[q * 4 + 0][r] = vb.x; Bs[q * 4 + 1][r] = vb.y;
            Bs[q * 4 + 2][r] = vb.z; Bs[q * 4 + 3][r] = vb.w;
        }
        __syncthreads();
#pragma unroll
        for (int kc2 = 0; kc2 < 16; kc2 += 8) {
            uint32_t af[4][4];    // [mi][reg]
            uint32_t bf[4][2];    // [ni][reg]
#pragma unroll
            for (int mi = 0; mi < 4; mi++) {
                int m = wm + mi * 16 + grp;
                af[mi][0] = As[kc2 + qk][m];
                af[mi][1] = As[kc2 + qk][m + 8];
                af[mi][2] = As[kc2 + 4 + qk][m];
                af[mi][3] = As[kc2 + 4 + qk][m + 8];
            }
#pragma unroll
            for (int ni = 0; ni < 4; ni++) {
                int n = wn + ni * 8 + grp;
                bf[ni][0] = Bs[kc2 + qk][n];
                bf[ni][1] = Bs[kc2 + 4 + qk][n];
            }
#pragma unroll
            for (int mi = 0; mi < 4; mi++)
#pragma unroll
                for (int ni = 0; ni < 4; ni++)
                    mma_bf16(acc[mi][ni], af[mi], bf[ni]);
        }
        __syncthreads();
    }

    // epilogue
    const float* __restrict__ bih = dir ? bihb : bihf;
    const float* __restrict__ bhh = dir ? bhhb : bhhf;
#pragma unroll
    for (int ni = 0; ni < 4; ni++) {
        int gate0 = g0 + wn + ni * 8 + 2 * qk;
        float bias0 = bih[gate0] + bhh[gate0];
        float bias1 = bih[gate0 + 1] + bhh[gate0 + 1];
        int g2w = (g0 + wn + ni * 8) / 2 + qk;
#pragma unroll
        for (int mi = 0; mi < 4; mi++) {
            int bA = wm + mi * 16 + grp;
            g_preB[dir][t][bA][g2w]     = pack_bf16(acc[mi][ni][0] + bias0, acc[mi][ni][1] + bias1);
            g_preB[dir][t][bA + 8][g2w] = pack_bf16(acc[mi][ni][2] + bias0, acc[mi][ni][3] + bias1);
        }
    }
}

// ---------------- 2) LSTM recurrence: 2-D partition (batch-block x gate-slice), mma bf16 ----------------
// 128 CTAs: dir = blk>>6; bblk = (blk>>3)&7 (16 batch rows); gs = blk&7 (32 hidden units).
// Sync group = 8 CTAs sharing (dir, bblk); each group has its own padded counter.
// Warp w owns 4 hidden units (16 gate cols); all warps share the CTA's 16-batch h block.
__global__ void __launch_bounds__(256) k_lstm3(
    const float* __restrict__ whf, const float* __restrict__ whb)
{
    const int dir  = blockIdx.x >> 6;
    const int sub  = blockIdx.x & 63;
    const int bblk = sub >> 3;
    const int gs   = sub & 7;
    const float* __restrict__ whh = dir ? whb : whf;

    const int tid  = threadIdx.x;
    const int wid  = tid >> 5;
    const int lane = tid & 31;
    const int grp  = lane >> 2;
    const int qk   = lane & 3;
    const int bm   = bblk * 16;             // CTA batch base (shared by all warps)
    const int m0w  = gs * 32 + wid * 4;     // warp's 4 hidden units

    // h staging: [k2 row 0..127][b col 0..15], stride 24 words (conflict-free)
    __shared__ uint32_t hsm[128 * 24];      // 12.3 KB

    // ---- B fragments (W_hh slice for this warp), persistent in registers ----
    uint32_t B0[2][16], B1[2][16];
#pragma unroll
    for (int nt = 0; nt < 2; nt++) {
        int c = nt * 8 + grp;                          // warp col 0..15
        int gcol = (c >> 2) * 256 + m0w + (c & 3);     // global gate
        const float* wr = whh + (size_t)gcol * Hn;
#pragma unroll
        for (int kb = 0; kb < 16; kb++) {
            float2 w0 = *(const float2*)(wr + kb * 16 + 2 * qk);
            float2 w1 = *(const float2*)(wr + kb * 16 + 8 + 2 * qk);
            B0[nt][kb] = pack_bf16(w0.x, w0.y);
            B1[nt][kb] = pack_bf16(w1.x, w1.y);
        }
    }

    float cst0 = 0.0f, cst1 = 0.0f;                   // cell state (2 per lane)
    const int rb      = (qk >= 2) ? 2 : 0;
    const int b_row   = bm + grp + ((qk >= 2) ? 8 : 0);
    const int m2w     = (m0w >> 1) + (qk & 1);
    const int hwrd    = dir * 128 + (m0w >> 1) + (qk & 1);  // hist word col
    unsigned long long* const barp = &g_bar[(dir * 8 + bblk) * 8];

    const int wrd0 = ((qk >> 1)) * 128 + m2w;       // nt=0 preB word
    const int wrd1 = (2 + (qk >> 1)) * 128 + m2w;   // nt=1 preB word

    // prefetch preB for t=0
    uint32_t pw[4];
    pw[0] = g_preB[dir][0][bm + grp][wrd0];
    pw[1] = g_preB[dir][0][bm + grp + 8][wrd0];
    pw[2] = g_preB[dir][0][bm + grp][wrd1];
    pw[3] = g_preB[dir][0][bm + grp + 8][wrd1];

    // per-thread staging coords: 2 uint4 per thread (512 uint4 = 128 rows x 4)
    const int sidx0 = tid * 2;

    for (int t = 0; t < Ln; t++) {
        float acc[2][4];
#pragma unroll
        for (int nt = 0; nt < 2; nt++)
#pragma unroll
            for (int r = 0; r < 4; r++) acc[nt][r] = 0.0f;

        if (t > 0) {
            const uint4* __restrict__ hp4 =
                (const uint4*)&g_hN[(t & 1) ^ 1][dir][0][0];   // row pitch 32 uint4
#pragma unroll
            for (int j = 0; j < 2; j++) {
                int idx = sidx0 + j;
                int r   = idx >> 2;          // k2 row 0..127
                int c4  = idx & 3;           // uint4 col within 16-word block
                uint4 v = __ldcg(hp4 + r * 32 + (bm >> 2) + c4);
                *(uint4*)&hsm[r * 24 + c4 * 4] = v;
            }
            __syncthreads();
#pragma unroll
            for (int kb = 0; kb < 16; kb++) {
                uint32_t a[4];
                const int r0 = (kb * 8 + qk) * 24;
                a[0] = hsm[r0 + grp];
                a[1] = hsm[r0 + grp + 8];
                a[2] = hsm[r0 + 96 + grp];        // +4 rows
                a[3] = hsm[r0 + 96 + grp + 8];
                uint32_t b0[2] = {B0[0][kb], B1[0][kb]};
                uint32_t b1[2] = {B0[1][kb], B1[1][kb]};
                mma_bf16(acc[0], a, b0);
                mma_bf16(acc[1], a, b1);
            }
        }

        // add pre-activations (prefetched)
        acc[0][0] += bflo(pw[0]); acc[0][1] += bfhi(pw[0]);
        acc[0][2] += bflo(pw[1]); acc[0][3] += bfhi(pw[1]);
        acc[1][0] += bflo(pw[2]); acc[1][1] += bfhi(pw[2]);
        acc[1][2] += bflo(pw[3]); acc[1][3] += bfhi(pw[3]);

        // exchange with lane^2: (i,g) <-> (f,o)
        float recv[2][4];
#pragma unroll
        for (int nt = 0; nt < 2; nt++)
#pragma unroll
            for (int r = 0; r < 4; r++)
                recv[nt][r] = __shfl_xor_sync(0xffffffffu, acc[nt][r], 2);

        const bool ig = (qk < 2);
        float h0, h1;
        {
            float i_ = ig ? acc[0][rb + 0] : recv[0][rb + 0];
            float f_ = ig ? recv[0][rb + 0] : acc[0][rb + 0];
            float g_ = ig ? acc[1][rb + 0] : recv[1][rb + 0];
            float o_ = ig ? recv[1][rb + 0] : acc[1][rb + 0];
            cst0 = sigf(f_) * cst0 + sigf(i_) * tanhfast(g_);
            h0 = sigf(o_) * tanhfast(cst0);
        }
        {
            float i_ = ig ? acc[0][rb + 1] : recv[0][rb + 1];
            float f_ = ig ? recv[0][rb + 1] : acc[0][rb + 1];
            float g_ = ig ? acc[1][rb + 1] : recv[1][rb + 1];
            float o_ = ig ? recv[1][rb + 1] : acc[1][rb + 1];
            cst1 = sigf(f_) * cst1 + sigf(i_) * tanhfast(g_);
            h1 = sigf(o_) * tanhfast(cst1);
        }

        // publish h: bf16x2 word for next step + bf16x2 history
        uint32_t hw = pack_bf16(h0, h1);
        __stcg(&g_hN[t & 1][dir][m2w][b_row], hw);
        const int rt = dir ? (Ln - 1 - t) : t;
        __stcg(&g_histB[rt][b_row][hwrd], hw);

        if (t != Ln - 1) {
            // prefetch next step's preB before the barrier (no dependency)
            pw[0] = __ldcg(&g_preB[dir][t + 1][bm + grp][wrd0]);
            pw[1] = __ldcg(&g_preB[dir][t + 1][bm + grp + 8][wrd0]);
            pw[2] = __ldcg(&g_preB[dir][t + 1][bm + grp][wrd1]);
            pw[3] = __ldcg(&g_preB[dir][t + 1][bm + grp + 8][wrd1]);
            // CG-style barrier over the 8 CTAs of this (dir, bblk) group
            __syncthreads();
            if (tid == 0) {
                unsigned long long v;
                asm volatile("atom.add.release.gpu.u64 %0, [%1], 1;"
                             : "=l"(v) : "l"(barp) : "memory");
                unsigned long long target = ((v >> 3) + 1ULL) << 3;   // 8 CTAs per group
                unsigned long long cur;
                while (true) {
                    asm volatile("ld.acquire.gpu.u64 %0, [%1];"
                                 : "=l"(cur) : "l"(barp) : "memory");
                    if (cur >= target) break;
                    __nanosleep(32);
                }
            }
            __syncthreads();
        }
    }
}

// ---------------- 3) emit GEMM (mma bf16): emit[b][t][k] = histB[t][b] @ wemb^T + b_emit ----------------
__global__ void __launch_bounds__(256) k_emit2(const float* __restrict__ bem)
{
    const int t = blockIdx.x;
    __shared__ uint32_t As[32][136];   // [k2][b]
    __shared__ uint32_t Bs[32][72];    // [k2][k-col]

    const int tid  = threadIdx.x;
    const int wid  = tid >> 5;
    const int lane = tid & 31;
    const int grp  = lane >> 2;
    const int qk   = lane & 3;
    const int wm   = wid * 16;          // warp batch base

    float acc[8][4];
#pragma unroll
    for (int nb = 0; nb < 8; nb++)
#pragma unroll
        for (int r = 0; r < 4; r++) acc[nb][r] = 0.0f;

    for (int c = 0; c < 8; c++) {                  // K chunks: 64 h (32 words)
        const int k0w = c * 32;
#pragma unroll
        for (int i = 0; i < 4; i++) {              // A: 128 rows x 32 words
            int idx = (i << 8) + tid;
            int r   = idx >> 3;                    // 0..127
            int q   = idx & 7;
            uint4 v = *(const uint4*)&g_histB[t][r][k0w + q * 4];
            As[q * 4 + 0][r] = v.x; As[q * 4 + 1][r] = v.y;
            As[q * 4 + 2][r] = v.z; As[q * 4 + 3][r] = v.w;
        }
#pragma unroll
        for (int i = 0; i < 2; i++) {              // B: 64 rows x 32 words
            int idx = (i << 8) + tid;
            int r   = idx >> 3;                    // 0..63
            int q   = idx & 7;
            uint4 v = *(const uint4*)&g_wemb[r][k0w + q * 4];
            Bs[q * 4 + 0][r] = v.x; Bs[q * 4 + 1][r] = v.y;
            Bs[q * 4 + 2][r] = v.z; Bs[q * 4 + 3][r] = v.w;
        }
        __syncthreads();
#pragma unroll
        for (int kb = 0; kb < 4; kb++) {
            int k2 = kb * 8;
            uint32_t a[4];
            a[0] = As[k2 + qk][wm + grp];
            a[1] = As[k2 + qk][wm + grp + 8];
            a[2] = As[k2 + 4 + qk][wm + grp];
            a[3] = As[k2 + 4 + qk][wm + grp + 8];
#pragma unroll
            for (int nb = 0; nb < 8; nb++) {
                uint32_t b[2] = {Bs[k2 + qk][nb * 8 + grp], Bs[k2 + 4 + qk][nb * 8 + grp]};
                mma_bf16(acc[nb], a, b);
            }
        }
        __syncthreads();
    }

#pragma unroll
    for (int nb = 0; nb < 8; nb++) {
        int k = nb * 8 + qk * 2;
        float b0 = bem[k], b1 = bem[k + 1];
        *(float2*)&g_emit[wm + grp][t][k]     = make_float2(acc[nb][0] + b0, acc[nb][1] + b1);
        *(float2*)&g_emit[wm + grp + 8][t][k] = make_float2(acc[nb][2] + b0, acc[nb][3] + b1);
    }
}

// ---------------- 4) CRF forward + gold score: warp per batch, reduction-free shift ----------------
__global__ void __launch_bounds__(32) k_crf(
    const int* __restrict__ labels,
    const float* __restrict__ trans,
    float* __restrict__ out)
{
    const int b = blockIdx.x;
    const int lane = threadIdx.x;
    __shared__ float ps[64];

    float eTc0[64], eTc1[64];
#pragma unroll 8
    for (int i = 0; i < 64; i++) {
        eTc0[i] = __expf(trans[i * 64 + lane]);
        eTc1[i] = __expf(trans[i * 64 + lane + 32]);
    }

    float d0 = g_emit[b][0][lane];
    float d1 = g_emit[b][0][lane + 32];
    float Cacc = 0.0f, Ckah = 0.0f;

    for (int t = 1; t < Ln; t++) {
        float c = __shfl_sync(0xffffffffu, d0, 0);
        ps[lane]      = __expf(d0 - c);
        ps[lane + 32] = __expf(d1 - c);
        __syncwarp();
        float s0a = 0.f, s0b = 0.f, s1a = 0.f, s1b = 0.f;
#pragma unroll
        for (int i = 0; i < 64; i += 2) {
            float pi = ps[i], pj = ps[i + 1];
            s0a = fmaf(pi, eTc0[i], s0a);
            s0b = fmaf(pj, eTc0[i + 1], s0b);
            s1a = fmaf(pi, eTc1[i], s1a);
            s1b = fmaf(pj, eTc1[i + 1], s1b);
        }
        d0 = g_emit[b][t][lane]      + __logf(s0a + s0b);
        d1 = g_emit[b][t][lane + 32] + __logf(s1a + s1b);
        float y = c - Ckah;
        float tt = Cacc + y;
        Ckah = (tt - Cacc) - y;
        Cacc = tt;
        __syncwarp();
    }

    float m = fmaxf(d0, d1);
#pragma unroll
    for (int o = 16; o > 0; o >>= 1)
        m = fmaxf(m, __shfl_xor_sync(0xffffffffu, m, o));
    float sp = __expf(d0 - m) + __expf(d1 - m);
#pragma unroll
    for (int o = 16; o > 0; o >>= 1)
        sp += __shfl_xor_sync(0xffffffffu, sp, o);
    float logz = m + __logf(sp) + Cacc;

    float gold = 0.0f;
    for (int t = lane; t < Ln; t += 32) {
        int lab = labels[b * Ln + t];
        gold += g_emit[b][t][lab];
        if (t < Ln - 1) {
            int lab2 = labels[b * Ln + t + 1];
            gold += trans[lab * 64 + lab2];
        }
    }
#pragma unroll
    for (int o = 16; o > 0; o >>= 1)
        gold += __shfl_xor_sync(0xffffffffu, gold, o);

    if (lane == 0) out[b] = logz - gold;
}

// ---------------- launch ----------------
extern "C" void kernel_launch(void* const* d_in, const int* in_sizes, int n_in,
                              void* d_out, int out_size)
{
    const float* x     = (const float*)d_in[0];
    const int*   lab   = (const int*)d_in[1];
    const float* wihf  = (const float*)d_in[2];
    const float* whhf  = (const float*)d_in[3];
    const float* bihf  = (const float*)d_in[4];
    const float* bhhf  = (const float*)d_in[5];
    const float* wihb  = (const float*)d_in[6];
    const float* whhb  = (const float*)d_in[7];
    const float* bihb  = (const float*)d_in[8];
    const float* bhhb  = (const float*)d_in[9];
    const float* wem   = (const float*)d_in[10];
    const float* bem   = (const float*)d_in[11];
    const float* trans = (const float*)d_in[12];
    float* out = (float*)d_out;

    k_cvt_x<<<16384, 256>>>(x);
    k_cvt_w<<<1088, 256>>>(wihf, wihb, wem);
    dim3 gg(8, 512, 2);
    k_gemm_bf16<<<gg, 256>>>(bihf, bhhf, bihb, bhhb);
    k_lstm3<<<128, 256>>>(whhf, whhb);
    k_emit2<<<512, 256>>>(bem);
    k_crf<<<128, 32>>>(lab, trans, out);
}

// round 12
// speedup vs baseline: 3.1012x; 1.0739x over previous
#include <cuda_runtime.h>
#include <cstdint>

#define Bn 128
#define Ln 512
#define En 512
#define Hn 256
#define G4 1024
#define Kn 64

// ---------------- scratch (static device allocations) ----------------
__device__ uint32_t g_preB[2][Ln][Bn][G4/2];   // 268MB: pre-activations bf16x2 [dir][t][b][gate_pair]
__device__ uint32_t g_histB[Ln][Bn][Hn];       // 67MB: concat hidden states bf16x2 [t][b][h_pair]
__device__ float g_emit[Bn][Ln][Kn];           // emissions [b][t][k]
__device__ uint32_t g_xb[Bn][Ln][En/2];        // 67MB: x in bf16x2
__device__ uint32_t g_wihb2[2][G4][En/2];      // W_ih bf16x2 (2MB)
__device__ uint32_t g_wemb[Kn][En/2];          // w_emit bf16x2 (64KB)

__device__ __forceinline__ float sigf(float x) {
    return 1.0f / (1.0f + __expf(-x));
}
__device__ __forceinline__ float tanhfast(float x) {
    float e = __expf(2.0f * x);
    return 1.0f - __fdividef(2.0f, e + 1.0f);
}

__device__ __forceinline__ uint32_t pack_bf16(float lo, float hi) {
    uint32_t r;
    asm("cvt.rn.bf16x2.f32 %0, %1, %2;" : "=r"(r) : "f"(hi), "f"(lo));
    return r;
}
__device__ __forceinline__ float bflo(uint32_t w) { return __uint_as_float(w << 16); }
__device__ __forceinline__ float bfhi(uint32_t w) { return __uint_as_float(w & 0xffff0000u); }

__device__ __forceinline__ void mma_bf16(float* d, const uint32_t* a, const uint32_t* b) {
    asm volatile(
        "mma.sync.aligned.m16n8k16.row.col.f32.bf16.bf16.f32 "
        "{%0,%1,%2,%3}, {%4,%5,%6,%7}, {%8,%9}, {%0,%1,%2,%3};"
        : "+f"(d[0]), "+f"(d[1]), "+f"(d[2]), "+f"(d[3])
        : "r"(a[0]), "r"(a[1]), "r"(a[2]), "r"(a[3]), "r"(b[0]), "r"(b[1]));
}

__device__ __forceinline__ uint32_t smem_u32(const void* p) {
    uint32_t a;
    asm("{ .reg .u64 t; cvta.to.shared.u64 t, %1; cvt.u32.u64 %0, t; }" : "=r"(a) : "l"(p));
    return a;
}

// ---------------- 0) prep: fp32 -> bf16x2 conversions ----------------
__global__ void __launch_bounds__(256) k_cvt_x(const float* __restrict__ x) {
    uint32_t* dst = &g_xb[0][0][0];
    int i = blockIdx.x * 512 + threadIdx.x * 2;     // 2 float4 per thread
#pragma unroll
    for (int j = 0; j < 2; j++) {
        int f = i + j;
        float4 v = *(const float4*)(x + (size_t)f * 4);
        *(uint2*)(dst + (size_t)f * 2) = make_uint2(pack_bf16(v.x, v.y), pack_bf16(v.z, v.w));
    }
}

#define WF4 131072      // 1024*512/4
__global__ void __launch_bounds__(256) k_cvt_w(
    const float* __restrict__ wf, const float* __restrict__ wb,
    const float* __restrict__ wem)
{
    int f = blockIdx.x * 256 + threadIdx.x;          // float4 index
    const float* src;
    uint32_t* dst;
    if (f < WF4)           { src = wf;  dst = &g_wihb2[0][0][0]; }
    else if (f < 2 * WF4)  { src = wb;  dst = &g_wihb2[1][0][0]; f -= WF4; }
    else                   { src = wem; dst = &g_wemb[0][0];     f -= 2 * WF4;
                             if (f >= Kn * En / 4) return; }
    float4 v = *(const float4*)(src + (size_t)f * 4);
    *(uint2*)(dst + (size_t)f * 2) = make_uint2(pack_bf16(v.x, v.y), pack_bf16(v.z, v.w));
}

// ---------------- 1) input GEMM (mma.sync bf16, bf16 operands): pre = x @ W_ih^T + b ----------------
__global__ void __launch_bounds__(256) k_gemm_bf16(
    const float* __restrict__ bihf, const float* __restrict__ bhhf,
    const float* __restrict__ bihb, const float* __restrict__ bhhb)
{
    const int gtile = blockIdx.x;           // 0..7
    const int t     = blockIdx.y;           // 0..511
    const int dir   = blockIdx.z;           // 0,1
    const int t_eff = dir ? (Ln - 1 - t) : t;
    const int g0 = gtile * 128;

    __shared__ uint32_t As[16][136];   // [k2][b]  bf16x2 (x)
    __shared__ uint32_t Bs[16][136];   // [k2][g]  bf16x2 (W)

    const int tid  = threadIdx.x;
    const int wid  = tid >> 5;
    const int lane = tid & 31;
    const int wm   = (wid >> 2) * 64;   // warp M (batch) base
    const int wn   = (wid & 3) * 32;    // warp N (gate) base
    const int grp  = lane >> 2;         // 0..7
    const int qk   = lane & 3;          // 0..3

    float acc[4][4][4];                 // [mi][ni][reg]
#pragma unroll
    for (int mi = 0; mi < 4; mi++)
#pragma unroll
        for (int ni = 0; ni < 4; ni++)
#pragma unroll
            for (int r = 0; r < 4; r++) acc[mi][ni][r] = 0.0f;

    for (int k0w = 0; k0w < En / 2; k0w += 16) {       // 16 words = 32 k per stage
#pragma unroll
        for (int i = 0; i < 2; i++) {
            int idx = (i << 8) + tid;        // 0..511
            int r   = idx >> 2;              // row 0..127
            int q   = idx & 3;               // quad of words
            uint4 va = *(const uint4*)&g_xb[r][t_eff][k0w + q * 4];
            As[q * 4 + 0][r] = va.x; As[q * 4 + 1][r] = va.y;
            As[q * 4 + 2][r] = va.z; As[q * 4 + 3][r] = va.w;
            uint4 vb = *(const uint4*)&g_wihb2[dir][g0 + r][k0w + q * 4];
            Bs[q * 4 + 0][r] = vb.x; Bs[q * 4 + 1][r] = vb.y;
            Bs[q * 4 + 2][r] = vb.z; Bs[q * 4 + 3][r] = vb.w;
        }
        __syncthreads();
#pragma unroll
        for (int kc2 = 0; kc2 < 16; kc2 += 8) {
            uint32_t af[4][4];    // [mi][reg]
            uint32_t bf[4][2];    // [ni][reg]
#pragma unroll
            for (int mi = 0; mi < 4; mi++) {
                int m = wm + mi * 16 + grp;
                af[mi][0] = As[kc2 + qk][m];
                af[mi][1] = As[kc2 + qk][m + 8];
                af[mi][2] = As[kc2 + 4 + qk][m];
                af[mi][3] = As[kc2 + 4 + qk][m + 8];
            }
#pragma unroll
            for (int ni = 0; ni < 4; ni++) {
                int n = wn + ni * 8 + grp;
                bf[ni][0] = Bs[kc2 + qk][n];
                bf[ni][1] = Bs[kc2 + 4 + qk][n];
            }
#pragma unroll
            for (int mi = 0; mi < 4; mi++)
#pragma unroll
                for (int ni = 0; ni < 4; ni++)
                    mma_bf16(acc[mi][ni], af[mi], bf[ni]);
        }
        __syncthreads();
    }

    // epilogue
    const float* __restrict__ bih = dir ? bihb : bihf;
    const float* __restrict__ bhh = dir ? bhhb : bhhf;
#pragma unroll
    for (int ni = 0; ni < 4; ni++) {
        int gate0 = g0 + wn + ni * 8 + 2 * qk;
        float bias0 = bih[gate0] + bhh[gate0];
        float bias1 = bih[gate0 + 1] + bhh[gate0 + 1];
        int g2w = (g0 + wn + ni * 8) / 2 + qk;
#pragma unroll
        for (int mi = 0; mi < 4; mi++) {
            int bA = wm + mi * 16 + grp;
            g_preB[dir][t][bA][g2w]     = pack_bf16(acc[mi][ni][0] + bias0, acc[mi][ni][1] + bias1);
            g_preB[dir][t][bA + 8][g2w] = pack_bf16(acc[mi][ni][2] + bias0, acc[mi][ni][3] + bias1);
        }
    }
}

// ---------------- 2) LSTM recurrence: 8-CTA cluster, DSMEM h-exchange, HW cluster barrier ----------------
// 128 CTAs in 16 clusters of 8. dir = blk>>6; bblk = (blk>>3)&7 (16 batch rows); gs = blk&7 = cluster rank.
// Each CTA computes 32 hidden units for its 16 batches; h words are store-multicast to all 8
// cluster CTAs' SMEM (double-buffered by step parity); barrier.cluster replaces the L2 flag.
// Last step: no remote stores (dead), and a trailing cluster barrier guards CTA exit.
__global__ void __launch_bounds__(256) __cluster_dims__(8, 1, 1) k_lstm4(
    const float* __restrict__ whf, const float* __restrict__ whb)
{
    const int dir  = blockIdx.x >> 6;
    const int sub  = blockIdx.x & 63;
    const int bblk = sub >> 3;
    const int gs   = sub & 7;                // == cluster rank
    const float* __restrict__ whh = dir ? whb : whf;

    const int tid  = threadIdx.x;
    const int wid  = tid >> 5;
    const int lane = tid & 31;
    const int grp  = lane >> 2;
    const int qk   = lane & 3;
    const int bm   = bblk * 16;              // CTA batch base
    const int m0w  = gs * 32 + wid * 4;      // warp's 4 hidden units

    // h staging, double-buffered: [parity][k2 row 0..127][b col 0..15], stride 24 (conflict-free reads)
    __shared__ uint32_t hsm[2][128 * 24];    // 24.6 KB

    // ---- B fragments (W_hh slice for this warp), persistent in registers ----
    uint32_t B0[2][16], B1[2][16];
#pragma unroll
    for (int nt = 0; nt < 2; nt++) {
        int c = nt * 8 + grp;                          // warp col 0..15
        int gcol = (c >> 2) * 256 + m0w + (c & 3);     // global gate
        const float* wr = whh + (size_t)gcol * Hn;
#pragma unroll
        for (int kb = 0; kb < 16; kb++) {
            float2 w0 = *(const float2*)(wr + kb * 16 + 2 * qk);
            float2 w1 = *(const float2*)(wr + kb * 16 + 8 + 2 * qk);
            B0[nt][kb] = pack_bf16(w0.x, w0.y);
            B1[nt][kb] = pack_bf16(w1.x, w1.y);
        }
    }

    float cst0 = 0.0f, cst1 = 0.0f;                   // cell state (2 per lane)
    const int rb      = (qk >= 2) ? 2 : 0;
    const int b_loc   = grp + ((qk >= 2) ? 8 : 0);    // local batch col 0..15
    const int b_row   = bm + b_loc;
    const int m2w     = gs * 16 + wid * 2 + (qk & 1); // global k2 row 0..127
    const int hwrd    = dir * 128 + m2w;              // hist word col

    const int wrd0 = ((qk >> 1)) * 128 + m2w;       // nt=0 preB word
    const int wrd1 = (2 + (qk >> 1)) * 128 + m2w;   // nt=1 preB word

    // this thread's h word address within a staging buffer (byte offsets, both parities)
    const uint32_t ha0 = smem_u32(&hsm[0][m2w * 24 + b_loc]);
    const uint32_t ha1 = smem_u32(&hsm[1][m2w * 24 + b_loc]);

    // prefetch preB for t=0
    uint32_t pw[4];
    pw[0] = g_preB[dir][0][bm + grp][wrd0];
    pw[1] = g_preB[dir][0][bm + grp + 8][wrd0];
    pw[2] = g_preB[dir][0][bm + grp][wrd1];
    pw[3] = g_preB[dir][0][bm + grp + 8][wrd1];

    for (int t = 0; t < Ln; t++) {
        float acc[2][4];
#pragma unroll
        for (int nt = 0; nt < 2; nt++)
#pragma unroll
            for (int r = 0; r < 4; r++) acc[nt][r] = 0.0f;

        if (t > 0) {
            const uint32_t* __restrict__ hb = &hsm[(t - 1) & 1][0];
#pragma unroll
            for (int kb = 0; kb < 16; kb++) {
                uint32_t a[4];
                const int r0 = (kb * 8 + qk) * 24;
                a[0] = hb[r0 + grp];
                a[1] = hb[r0 + grp + 8];
                a[2] = hb[r0 + 96 + grp];        // +4 rows
                a[3] = hb[r0 + 96 + grp + 8];
                uint32_t b0[2] = {B0[0][kb], B1[0][kb]};
                uint32_t b1[2] = {B0[1][kb], B1[1][kb]};
                mma_bf16(acc[0], a, b0);
                mma_bf16(acc[1], a, b1);
            }
        }

        // add pre-activations (prefetched)
        acc[0][0] += bflo(pw[0]); acc[0][1] += bfhi(pw[0]);
        acc[0][2] += bflo(pw[1]); acc[0][3] += bfhi(pw[1]);
        acc[1][0] += bflo(pw[2]); acc[1][1] += bfhi(pw[2]);
        acc[1][2] += bflo(pw[3]); acc[1][3] += bfhi(pw[3]);

        // exchange with lane^2: (i,g) <-> (f,o)
        float recv[2][4];
#pragma unroll
        for (int nt = 0; nt < 2; nt++)
#pragma unroll
            for (int r = 0; r < 4; r++)
                recv[nt][r] = __shfl_xor_sync(0xffffffffu, acc[nt][r], 2);

        const bool ig = (qk < 2);
        float h0, h1;
        {
            float i_ = ig ? acc[0][rb + 0] : recv[0][rb + 0];
            float f_ = ig ? recv[0][rb + 0] : acc[0][rb + 0];
            float g_ = ig ? acc[1][rb + 0] : recv[1][rb + 0];
            float o_ = ig ? recv[1][rb + 0] : acc[1][rb + 0];
            cst0 = sigf(f_) * cst0 + sigf(i_) * tanhfast(g_);
            h0 = sigf(o_) * tanhfast(cst0);
        }
        {
            float i_ = ig ? acc[0][rb + 1] : recv[0][rb + 1];
            float f_ = ig ? recv[0][rb + 1] : acc[0][rb + 1];
            float g_ = ig ? acc[1][rb + 1] : recv[1][rb + 1];
            float o_ = ig ? recv[1][rb + 1] : acc[1][rb + 1];
            cst1 = sigf(f_) * cst1 + sigf(i_) * tanhfast(g_);
            h1 = sigf(o_) * tanhfast(cst1);
        }

        const uint32_t hw = pack_bf16(h0, h1);
        // bf16x2 history (global)
        const int rt = dir ? (Ln - 1 - t) : t;
        __stcg(&g_histB[rt][b_row][hwrd], hw);

        if (t != Ln - 1) {
            // publish h: multicast word to all 8 cluster CTAs' staging buffer (parity t&1).
            // Skipped on the last step: the stores would be dead AND could land in a
            // peer CTA's SMEM after that CTA exits (launch failure).
            const uint32_t laddr = (t & 1) ? ha1 : ha0;
#pragma unroll
            for (int r = 0; r < 8; r++) {
                uint32_t raddr;
                asm("mapa.shared::cluster.u32 %0, %1, %2;" : "=r"(raddr) : "r"(laddr), "r"(r));
                asm volatile("st.shared::cluster.u32 [%0], %1;" :: "r"(raddr), "r"(hw) : "memory");
            }
            // prefetch next step's preB before the barrier (no dependency)
            pw[0] = __ldcg(&g_preB[dir][t + 1][bm + grp][wrd0]);
            pw[1] = __ldcg(&g_preB[dir][t + 1][bm + grp + 8][wrd0]);
            pw[2] = __ldcg(&g_preB[dir][t + 1][bm + grp][wrd1]);
            pw[3] = __ldcg(&g_preB[dir][t + 1][bm + grp + 8][wrd1]);
            // HW cluster barrier: orders DSMEM stores (arrive=release, wait=acquire)
            asm volatile("barrier.cluster.arrive.aligned;" ::: "memory");
            asm volatile("barrier.cluster.wait.aligned;" ::: "memory");
        }
    }

    // trailing cluster barrier: no CTA exits while any peer's remote traffic could be in flight
    asm volatile("barrier.cluster.arrive.aligned;" ::: "memory");
    asm volatile("barrier.cluster.wait.aligned;" ::: "memory");
}

// ---------------- 3) emit GEMM (mma bf16): emit[b][t][k] = histB[t][b] @ wemb^T + b_emit ----------------
__global__ void __launch_bounds__(256) k_emit2(const float* __restrict__ bem)
{
    const int t = blockIdx.x;
    __shared__ uint32_t As[32][136];   // [k2][b]
    __shared__ uint32_t Bs[32][72];    // [k2][k-col]

    const int tid  = threadIdx.x;
    const int wid  = tid >> 5;
    const int lane = tid & 31;
    const int grp  = lane >> 2;
    const int qk   = lane & 3;
    const int wm   = wid * 16;          // warp batch base

    float acc[8][4];
#pragma unroll
    for (int nb = 0; nb < 8; nb++)
#pragma unroll
        for (int r = 0; r < 4; r++) acc[nb][r] = 0.0f;

    for (int c = 0; c < 8; c++) {                  // K chunks: 64 h (32 words)
        const int k0w = c * 32;
#pragma unroll
        for (int i = 0; i < 4; i++) {              // A: 128 rows x 32 words
            int idx = (i << 8) + tid;
            int r   = idx >> 3;                    // 0..127
            int q   = idx & 7;
            uint4 v = *(const uint4*)&g_histB[t][r][k0w + q * 4];
            As[q * 4 + 0][r] = v.x; As[q * 4 + 1][r] = v.y;
            As[q * 4 + 2][r] = v.z; As[q * 4 + 3][r] = v.w;
        }
#pragma unroll
        for (int i = 0; i < 2; i++) {              // B: 64 rows x 32 words
            int idx = (i << 8) + tid;
            int r   = idx >> 3;                    // 0..63
            int q   = idx & 7;
            uint4 v = *(const uint4*)&g_wemb[r][k0w + q * 4];
            Bs[q * 4 + 0][r] = v.x; Bs[q * 4 + 1][r] = v.y;
            Bs[q * 4 + 2][r] = v.z; Bs[q * 4 + 3][r] = v.w;
        }
        __syncthreads();
#pragma unroll
        for (int kb = 0; kb < 4; kb++) {
            int k2 = kb * 8;
            uint32_t a[4];
            a[0] = As[k2 + qk][wm + grp];
            a[1] = As[k2 + qk][wm + grp + 8];
            a[2] = As[k2 + 4 + qk][wm + grp];
            a[3] = As[k2 + 4 + qk][wm + grp + 8];
#pragma unroll
            for (int nb = 0; nb < 8; nb++) {
                uint32_t b[2] = {Bs[k2 + qk][nb * 8 + grp], Bs[k2 + 4 + qk][nb * 8 + grp]};
                mma_bf16(acc[nb], a, b);
            }
        }
        __syncthreads();
    }

#pragma unroll
    for (int nb = 0; nb < 8; nb++) {
        int k = nb * 8 + qk * 2;
        float b0 = bem[k], b1 = bem[k + 1];
        *(float2*)&g_emit[wm + grp][t][k]     = make_float2(acc[nb][0] + b0, acc[nb][1] + b1);
        *(float2*)&g_emit[wm + grp + 8][t][k] = make_float2(acc[nb][2] + b0, acc[nb][3] + b1);
    }
}

// ---------------- 4) CRF forward + gold score: warp per batch, reduction-free shift ----------------
__global__ void __launch_bounds__(32) k_crf(
    const int* __restrict__ labels,
    const float* __restrict__ trans,
    float* __restrict__ out)
{
    const int b = blockIdx.x;
    const int lane = threadIdx.x;
    __shared__ float ps[64];

    float eTc0[64], eTc1[64];
#pragma unroll 8
    for (int i = 0; i < 64; i++) {
        eTc0[i] = __expf(trans[i * 64 + lane]);
        eTc1[i] = __expf(trans[i * 64 + lane + 32]);
    }

    float d0 = g_emit[b][0][lane];
    float d1 = g_emit[b][0][lane + 32];
    float Cacc = 0.0f, Ckah = 0.0f;

    for (int t = 1; t < Ln; t++) {
        float c = __shfl_sync(0xffffffffu, d0, 0);
        ps[lane]      = __expf(d0 - c);
        ps[lane + 32] = __expf(d1 - c);
        __syncwarp();
        float s0a = 0.f, s0b = 0.f, s1a = 0.f, s1b = 0.f;
#pragma unroll
        for (int i = 0; i < 64; i += 2) {
            float pi = ps[i], pj = ps[i + 1];
            s0a = fmaf(pi, eTc0[i], s0a);
            s0b = fmaf(pj, eTc0[i + 1], s0b);
            s1a = fmaf(pi, eTc1[i], s1a);
            s1b = fmaf(pj, eTc1[i + 1], s1b);
        }
        d0 = g_emit[b][t][lane]      + __logf(s0a + s0b);
        d1 = g_emit[b][t][lane + 32] + __logf(s1a + s1b);
        float y = c - Ckah;
        float tt = Cacc + y;
        Ckah = (tt - Cacc) - y;
        Cacc = tt;
        __syncwarp();
    }

    float m = fmaxf(d0, d1);
#pragma unroll
    for (int o = 16; o > 0; o >>= 1)
        m = fmaxf(m, __shfl_xor_sync(0xffffffffu, m, o));
    float sp = __expf(d0 - m) + __expf(d1 - m);
#pragma unroll
    for (int o = 16; o > 0; o >>= 1)
        sp += __shfl_xor_sync(0xffffffffu, sp, o);
    float logz = m + __logf(sp) + Cacc;

    float gold = 0.0f;
    for (int t = lane; t < Ln; t += 32) {
        int lab = labels[b * Ln + t];
        gold += g_emit[b][t][lab];
        if (t < Ln - 1) {
            int lab2 = labels[b * Ln + t + 1];
            gold += trans[lab * 64 + lab2];
        }
    }
#pragma unroll
    for (int o = 16; o > 0; o >>= 1)
        gold += __shfl_xor_sync(0xffffffffu, gold, o);

    if (lane == 0) out[b] = logz - gold;
}

// ---------------- launch ----------------
extern "C" void kernel_launch(void* const* d_in, const int* in_sizes, int n_in,
                              void* d_out, int out_size)
{
    const float* x     = (const float*)d_in[0];
    const int*   lab   = (const int*)d_in[1];
    const float* wihf  = (const float*)d_in[2];
    const float* whhf  = (const float*)d_in[3];
    const float* bihf  = (const float*)d_in[4];
    const float* bhhf  = (const float*)d_in[5];
    const float* wihb  = (const float*)d_in[6];
    const float* whhb  = (const float*)d_in[7];
    const float* bihb  = (const float*)d_in[8];
    const float* bhhb  = (const float*)d_in[9];
    const float* wem   = (const float*)d_in[10];
    const float* bem   = (const float*)d_in[11];
    const float* trans = (const float*)d_in[12];
    float* out = (float*)d_out;

    k_cvt_x<<<16384, 256>>>(x);
    k_cvt_w<<<1088, 256>>>(wihf, wihb, wem);
    dim3 gg(8, 512, 2);
    k_gemm_bf16<<<gg, 256>>>(bihf, bhhf, bihb, bhhb);
    k_lstm4<<<128, 256>>>(whhf, whhb);
    k_emit2<<<512, 256>>>(bem);
    k_crf<<<128, 32>>>(lab, trans, out);
}

// round 13
// speedup vs baseline: 3.2075x; 1.0343x over previous
#include <cuda_runtime.h>
#include <cstdint>

#define Bn 128
#define Ln 512
#define En 512
#define Hn 256
#define G4 1024
#define Kn 64

// ---------------- scratch (static device allocations) ----------------
__device__ uint32_t g_preB[2][Ln][Bn][G4/2];   // 268MB: pre-activations bf16x2 [dir][t][b][gate_pair]
__device__ uint32_t g_histB[Ln][Bn][Hn];       // 67MB: concat hidden states bf16x2 [t][b][h_pair]
__device__ float g_emit[Bn][Ln][Kn];           // emissions [b][t][k]
__device__ uint32_t g_xb[Bn][Ln][En/2];        // 67MB: x in bf16x2
__device__ uint32_t g_wihb2[2][G4][En/2];      // W_ih bf16x2 (2MB)
__device__ uint32_t g_wemb[Kn][En/2];          // w_emit bf16x2 (64KB)

__device__ __forceinline__ float sigf(float x) {
    return 1.0f / (1.0f + __expf(-x));
}
__device__ __forceinline__ float tanhfast(float x) {
    float e = __expf(2.0f * x);
    return 1.0f - __fdividef(2.0f, e + 1.0f);
}

__device__ __forceinline__ uint32_t pack_bf16(float lo, float hi) {
    uint32_t r;
    asm("cvt.rn.bf16x2.f32 %0, %1, %2;" : "=r"(r) : "f"(hi), "f"(lo));
    return r;
}
__device__ __forceinline__ float bflo(uint32_t w) { return __uint_as_float(w << 16); }
__device__ __forceinline__ float bfhi(uint32_t w) { return __uint_as_float(w & 0xffff0000u); }

__device__ __forceinline__ void mma_bf16(float* d, const uint32_t* a, const uint32_t* b) {
    asm volatile(
        "mma.sync.aligned.m16n8k16.row.col.f32.bf16.bf16.f32 "
        "{%0,%1,%2,%3}, {%4,%5,%6,%7}, {%8,%9}, {%0,%1,%2,%3};"
        : "+f"(d[0]), "+f"(d[1]), "+f"(d[2]), "+f"(d[3])
        : "r"(a[0]), "r"(a[1]), "r"(a[2]), "r"(a[3]), "r"(b[0]), "r"(b[1]));
}

__device__ __forceinline__ uint32_t smem_u32(const void* p) {
    uint32_t a;
    asm("{ .reg .u64 t; cvta.to.shared.u64 t, %1; cvt.u32.u64 %0, t; }" : "=r"(a) : "l"(p));
    return a;
}

// ---------------- 0) prep: fp32 -> bf16x2 conversions ----------------
__global__ void __launch_bounds__(256) k_cvt_x(const float* __restrict__ x) {
    uint32_t* dst = &g_xb[0][0][0];
    int i = blockIdx.x * 512 + threadIdx.x * 2;     // 2 float4 per thread
#pragma unroll
    for (int j = 0; j < 2; j++) {
        int f = i + j;
        float4 v = *(const float4*)(x + (size_t)f * 4);
        *(uint2*)(dst + (size_t)f * 2) = make_uint2(pack_bf16(v.x, v.y), pack_bf16(v.z, v.w));
    }
}

#define WF4 131072      // 1024*512/4
__global__ void __launch_bounds__(256) k_cvt_w(
    const float* __restrict__ wf, const float* __restrict__ wb,
    const float* __restrict__ wem)
{
    int f = blockIdx.x * 256 + threadIdx.x;          // float4 index
    const float* src;
    uint32_t* dst;
    if (f < WF4)           { src = wf;  dst = &g_wihb2[0][0][0]; }
    else if (f < 2 * WF4)  { src = wb;  dst = &g_wihb2[1][0][0]; f -= WF4; }
    else                   { src = wem; dst = &g_wemb[0][0];     f -= 2 * WF4;
                             if (f >= Kn * En / 4) return; }
    float4 v = *(const float4*)(src + (size_t)f * 4);
    *(uint2*)(dst + (size_t)f * 2) = make_uint2(pack_bf16(v.x, v.y), pack_bf16(v.z, v.w));
}

__global__ void k_nop() {}

// ---------------- 1) input GEMM (mma.sync bf16, double-buffered + reg prefetch) ----------------
// C tile: M=128 batch x N=128 gates, K=512 in 16 stages of 32 (staging identical to R12);
// stage s+1 operands are LDG-prefetched into registers while stage s runs mma.
__global__ void __launch_bounds__(256) k_gemm_bf16(
    const float* __restrict__ bihf, const float* __restrict__ bhhf,
    const float* __restrict__ bihb, const float* __restrict__ bhhb)
{
    const int gtile = blockIdx.x;           // 0..7
    const int t     = blockIdx.y;           // 0..511
    const int dir   = blockIdx.z;           // 0,1
    const int t_eff = dir ? (Ln - 1 - t) : t;
    const int g0 = gtile * 128;

    __shared__ uint32_t As[2][16][136];   // [buf][k2][b]  bf16x2 (x)
    __shared__ uint32_t Bs[2][16][136];   // [buf][k2][g]  bf16x2 (W)

    const int tid  = threadIdx.x;
    const int wid  = tid >> 5;
    const int lane = tid & 31;
    const int wm   = (wid >> 2) * 64;   // warp M (batch) base
    const int wn   = (wid & 3) * 32;    // warp N (gate) base
    const int grp  = lane >> 2;         // 0..7
    const int qk   = lane & 3;          // 0..3

    // per-thread load coords (2 uint4 per operand per stage), same mapping as R12
    const int r0 = tid >> 2;            // 0..63
    const int r1 = (256 + tid) >> 2;    // 64..127
    const int q  = tid & 3;
    const uint32_t* __restrict__ xa0 = &g_xb[r0][t_eff][q * 4];
    const uint32_t* __restrict__ xa1 = &g_xb[r1][t_eff][q * 4];
    const uint32_t* __restrict__ wa0 = &g_wihb2[dir][g0 + r0][q * 4];
    const uint32_t* __restrict__ wa1 = &g_wihb2[dir][g0 + r1][q * 4];

    uint4 va0, va1, vb0, vb1;
#define LOADG(s) do {                                      \
        va0 = *(const uint4*)(xa0 + (s) * 16);             \
        va1 = *(const uint4*)(xa1 + (s) * 16);             \
        vb0 = *(const uint4*)(wa0 + (s) * 16);             \
        vb1 = *(const uint4*)(wa1 + (s) * 16);             \
    } while (0)
#define STOREG(bu) do {                                                        \
        const int k2s = q * 4;                                                 \
        As[bu][k2s + 0][r0] = va0.x; As[bu][k2s + 1][r0] = va0.y;              \
        As[bu][k2s + 2][r0] = va0.z; As[bu][k2s + 3][r0] = va0.w;              \
        As[bu][k2s + 0][r1] = va1.x; As[bu][k2s + 1][r1] = va1.y;              \
        As[bu][k2s + 2][r1] = va1.z; As[bu][k2s + 3][r1] = va1.w;              \
        Bs[bu][k2s + 0][r0] = vb0.x; Bs[bu][k2s + 1][r0] = vb0.y;              \
        Bs[bu][k2s + 2][r0] = vb0.z; Bs[bu][k2s + 3][r0] = vb0.w;              \
        Bs[bu][k2s + 0][r1] = vb1.x; Bs[bu][k2s + 1][r1] = vb1.y;              \
        Bs[bu][k2s + 2][r1] = vb1.z; Bs[bu][k2s + 3][r1] = vb1.w;              \
    } while (0)

    float acc[4][4][4];                 // [mi][ni][reg]
#pragma unroll
    for (int mi = 0; mi < 4; mi++)
#pragma unroll
        for (int ni = 0; ni < 4; ni++)
#pragma unroll
            for (int r = 0; r < 4; r++) acc[mi][ni][r] = 0.0f;

    LOADG(0);
    STOREG(0);
    __syncthreads();

    for (int s = 0; s < 16; s++) {
        const int cur = s & 1;
        if (s < 15) LOADG(s + 1);       // overlap with this stage's mma

#pragma unroll
        for (int kc2 = 0; kc2 < 16; kc2 += 8) {
            uint32_t af[4][4];    // [mi][reg]
            uint32_t bf[4][2];    // [ni][reg]
#pragma unroll
            for (int mi = 0; mi < 4; mi++) {
                int m = wm + mi * 16 + grp;
                af[mi][0] = As[cur][kc2 + qk][m];
                af[mi][1] = As[cur][kc2 + qk][m + 8];
                af[mi][2] = As[cur][kc2 + 4 + qk][m];
                af[mi][3] = As[cur][kc2 + 4 + qk][m + 8];
            }
#pragma unroll
            for (int ni = 0; ni < 4; ni++) {
                int n = wn + ni * 8 + grp;
                bf[ni][0] = Bs[cur][kc2 + qk][n];
                bf[ni][1] = Bs[cur][kc2 + 4 + qk][n];
            }
#pragma unroll
            for (int mi = 0; mi < 4; mi++)
#pragma unroll
                for (int ni = 0; ni < 4; ni++)
                    mma_bf16(acc[mi][ni], af[mi], bf[ni]);
        }

        if (s < 15) {
            STOREG((s + 1) & 1);
            __syncthreads();
        }
    }
#undef LOADG
#undef STOREG

    // epilogue
    const float* __restrict__ bih = dir ? bihb : bihf;
    const float* __restrict__ bhh = dir ? bhhb : bhhf;
#pragma unroll
    for (int ni = 0; ni < 4; ni++) {
        int gate0 = g0 + wn + ni * 8 + 2 * qk;
        float bias0 = bih[gate0] + bhh[gate0];
        float bias1 = bih[gate0 + 1] + bhh[gate0 + 1];
        int g2w = (g0 + wn + ni * 8) / 2 + qk;
#pragma unroll
        for (int mi = 0; mi < 4; mi++) {
            int bA = wm + mi * 16 + grp;
            g_preB[dir][t][bA][g2w]     = pack_bf16(acc[mi][ni][0] + bias0, acc[mi][ni][1] + bias1);
            g_preB[dir][t][bA + 8][g2w] = pack_bf16(acc[mi][ni][2] + bias0, acc[mi][ni][3] + bias1);
        }
    }
}

// ---------------- 2) LSTM recurrence: 8-CTA cluster, DSMEM h-exchange, split acc chains ----------------
__global__ void __launch_bounds__(256) __cluster_dims__(8, 1, 1) k_lstm4(
    const float* __restrict__ whf, const float* __restrict__ whb)
{
    const int dir  = blockIdx.x >> 6;
    const int sub  = blockIdx.x & 63;
    const int bblk = sub >> 3;
    const int gs   = sub & 7;                // == cluster rank
    const float* __restrict__ whh = dir ? whb : whf;

    const int tid  = threadIdx.x;
    const int wid  = tid >> 5;
    const int lane = tid & 31;
    const int grp  = lane >> 2;
    const int qk   = lane & 3;
    const int bm   = bblk * 16;              // CTA batch base
    const int m0w  = gs * 32 + wid * 4;      // warp's 4 hidden units

    // h staging, double-buffered: [parity][k2 row 0..127][b col 0..15], stride 24 (conflict-free reads)
    __shared__ uint32_t hsm[2][128 * 24];    // 24.6 KB

    // ---- B fragments (W_hh slice for this warp), persistent in registers ----
    uint32_t B0[2][16], B1[2][16];
#pragma unroll
    for (int nt = 0; nt < 2; nt++) {
        int c = nt * 8 + grp;                          // warp col 0..15
        int gcol = (c >> 2) * 256 + m0w + (c & 3);     // global gate
        const float* wr = whh + (size_t)gcol * Hn;
#pragma unroll
        for (int kb = 0; kb < 16; kb++) {
            float2 w0 = *(const float2*)(wr + kb * 16 + 2 * qk);
            float2 w1 = *(const float2*)(wr + kb * 16 + 8 + 2 * qk);
            B0[nt][kb] = pack_bf16(w0.x, w0.y);
            B1[nt][kb] = pack_bf16(w1.x, w1.y);
        }
    }

    float cst0 = 0.0f, cst1 = 0.0f;                   // cell state (2 per lane)
    const int rb      = (qk >= 2) ? 2 : 0;
    const int b_loc   = grp + ((qk >= 2) ? 8 : 0);    // local batch col 0..15
    const int b_row   = bm + b_loc;
    const int m2w     = gs * 16 + wid * 2 + (qk & 1); // global k2 row 0..127
    const int hwrd    = dir * 128 + m2w;              // hist word col

    const int wrd0 = ((qk >> 1)) * 128 + m2w;       // nt=0 preB word
    const int wrd1 = (2 + (qk >> 1)) * 128 + m2w;   // nt=1 preB word

    const uint32_t ha0 = smem_u32(&hsm[0][m2w * 24 + b_loc]);
    const uint32_t ha1 = smem_u32(&hsm[1][m2w * 24 + b_loc]);

    // prefetch preB for t=0
    uint32_t pw[4];
    pw[0] = g_preB[dir][0][bm + grp][wrd0];
    pw[1] = g_preB[dir][0][bm + grp + 8][wrd0];
    pw[2] = g_preB[dir][0][bm + grp][wrd1];
    pw[3] = g_preB[dir][0][bm + grp + 8][wrd1];

    for (int t = 0; t < Ln; t++) {
        float acc[2][4], acd[2][4];      // even-kb and odd-kb accumulator chains
#pragma unroll
        for (int nt = 0; nt < 2; nt++)
#pragma unroll
            for (int r = 0; r < 4; r++) { acc[nt][r] = 0.0f; acd[nt][r] = 0.0f; }

        if (t > 0) {
            const uint32_t* __restrict__ hb = &hsm[(t - 1) & 1][0];
#pragma unroll
            for (int kb = 0; kb < 16; kb++) {
                uint32_t a[4];
                const int r0 = (kb * 8 + qk) * 24;
                a[0] = hb[r0 + grp];
                a[1] = hb[r0 + grp + 8];
                a[2] = hb[r0 + 96 + grp];        // +4 rows
                a[3] = hb[r0 + 96 + grp + 8];
                uint32_t b0[2] = {B0[0][kb], B1[0][kb]};
                uint32_t b1[2] = {B0[1][kb], B1[1][kb]};
                float* d0 = (kb & 1) ? acd[0] : acc[0];
                float* d1 = (kb & 1) ? acd[1] : acc[1];
                mma_bf16(d0, a, b0);
                mma_bf16(d1, a, b1);
            }
#pragma unroll
            for (int nt = 0; nt < 2; nt++)
#pragma unroll
                for (int r = 0; r < 4; r++) acc[nt][r] += acd[nt][r];
        }

        // add pre-activations (prefetched)
        acc[0][0] += bflo(pw[0]); acc[0][1] += bfhi(pw[0]);
        acc[0][2] += bflo(pw[1]); acc[0][3] += bfhi(pw[1]);
        acc[1][0] += bflo(pw[2]); acc[1][1] += bfhi(pw[2]);
        acc[1][2] += bflo(pw[3]); acc[1][3] += bfhi(pw[3]);

        // exchange with lane^2: (i,g) <-> (f,o)
        float recv[2][4];
#pragma unroll
        for (int nt = 0; nt < 2; nt++)
#pragma unroll
            for (int r = 0; r < 4; r++)
                recv[nt][r] = __shfl_xor_sync(0xffffffffu, acc[nt][r], 2);

        const bool ig = (qk < 2);
        float h0, h1;
        {
            float i_ = ig ? acc[0][rb + 0] : recv[0][rb + 0];
            float f_ = ig ? recv[0][rb + 0] : acc[0][rb + 0];
            float g_ = ig ? acc[1][rb + 0] : recv[1][rb + 0];
            float o_ = ig ? recv[1][rb + 0] : acc[1][rb + 0];
            cst0 = sigf(f_) * cst0 + sigf(i_) * tanhfast(g_);
            h0 = sigf(o_) * tanhfast(cst0);
        }
        {
            float i_ = ig ? acc[0][rb + 1] : recv[0][rb + 1];
            float f_ = ig ? recv[0][rb + 1] : acc[0][rb + 1];
            float g_ = ig ? acc[1][rb + 1] : recv[1][rb + 1];
            float o_ = ig ? recv[1][rb + 1] : acc[1][rb + 1];
            cst1 = sigf(f_) * cst1 + sigf(i_) * tanhfast(g_);
            h1 = sigf(o_) * tanhfast(cst1);
        }

        const uint32_t hw = pack_bf16(h0, h1);
        const int rt = dir ? (Ln - 1 - t) : t;
        __stcg(&g_histB[rt][b_row][hwrd], hw);

        if (t != Ln - 1) {
            // multicast h word to all 8 cluster CTAs (skipped on the last step: dead +
            // would race peer CTA exit)
            const uint32_t laddr = (t & 1) ? ha1 : ha0;
#pragma unroll
            for (int r = 0; r < 8; r++) {
                uint32_t raddr;
                asm("mapa.shared::cluster.u32 %0, %1, %2;" : "=r"(raddr) : "r"(laddr), "r"(r));
                asm volatile("st.shared::cluster.u32 [%0], %1;" :: "r"(raddr), "r"(hw) : "memory");
            }
            // prefetch next step's preB before the barrier (no dependency)
            pw[0] = __ldcg(&g_preB[dir][t + 1][bm + grp][wrd0]);
            pw[1] = __ldcg(&g_preB[dir][t + 1][bm + grp + 8][wrd0]);
            pw[2] = __ldcg(&g_preB[dir][t + 1][bm + grp][wrd1]);
            pw[3] = __ldcg(&g_preB[dir][t + 1][bm + grp + 8][wrd1]);
            asm volatile("barrier.cluster.arrive.aligned;" ::: "memory");
            asm volatile("barrier.cluster.wait.aligned;" ::: "memory");
        }
    }

    // trailing cluster barrier: no CTA exits while any peer's remote traffic could be in flight
    asm volatile("barrier.cluster.arrive.aligned;" ::: "memory");
    asm volatile("barrier.cluster.wait.aligned;" ::: "memory");
}

// ---------------- 3) emit GEMM (mma bf16): emit[b][t][k] = histB[t][b] @ wemb^T + b_emit ----------------
__global__ void __launch_bounds__(256) k_emit2(const float* __restrict__ bem)
{
    const int t = blockIdx.x;
    __shared__ uint32_t As[32][136];   // [k2][b]
    __shared__ uint32_t Bs[32][72];    // [k2][k-col]

    const int tid  = threadIdx.x;
    const int wid  = tid >> 5;
    const int lane = tid & 31;
    const int grp  = lane >> 2;
    const int qk   = lane & 3;
    const int wm   = wid * 16;          // warp batch base

    float acc[8][4];
#pragma unroll
    for (int nb = 0; nb < 8; nb++)
#pragma unroll
        for (int r = 0; r < 4; r++) acc[nb][r] = 0.0f;

    for (int c = 0; c < 8; c++) {                  // K chunks: 64 h (32 words)
        const int k0w = c * 32;
#pragma unroll
        for (int i = 0; i < 4; i++) {              // A: 128 rows x 32 words
            int idx = (i << 8) + tid;
            int r   = idx >> 3;                    // 0..127
            int q   = idx & 7;
            uint4 v = *(const uint4*)&g_histB[t][r][k0w + q * 4];
            As[q * 4 + 0][r] = v.x; As[q * 4 + 1][r] = v.y;
            As[q * 4 + 2][r] = v.z; As[q * 4 + 3][r] = v.w;
        }
#pragma unroll
        for (int i = 0; i < 2; i++) {              // B: 64 rows x 32 words
            int idx = (i << 8) + tid;
            int r   = idx >> 3;                    // 0..63
            int q   = idx & 7;
            uint4 v = *(const uint4*)&g_wemb[r][k0w + q * 4];
            Bs[q * 4 + 0][r] = v.x; Bs[q * 4 + 1][r] = v.y;
            Bs[q * 4 + 2][r] = v.z; Bs[q * 4 + 3][r] = v.w;
        }
        __syncthreads();
#pragma unroll
        for (int kb = 0; kb < 4; kb++) {
            int k2 = kb * 8;
            uint32_t a[4];
            a[0] = As[k2 + qk][wm + grp];
            a[1] = As[k2 + qk][wm + grp + 8];
            a[2] = As[k2 + 4 + qk][wm + grp];
            a[3] = As[k2 + 4 + qk][wm + grp + 8];
#pragma unroll
            for (int nb = 0; nb < 8; nb++) {
                uint32_t b[2] = {Bs[k2 + qk][nb * 8 + grp], Bs[k2 + 4 + qk][nb * 8 + grp]};
                mma_bf16(acc[nb], a, b);
            }
        }
        __syncthreads();
    }

#pragma unroll
    for (int nb = 0; nb < 8; nb++) {
        int k = nb * 8 + qk * 2;
        float b0 = bem[k], b1 = bem[k + 1];
        *(float2*)&g_emit[wm + grp][t][k]     = make_float2(acc[nb][0] + b0, acc[nb][1] + b1);
        *(float2*)&g_emit[wm + grp + 8][t][k] = make_float2(acc[nb][2] + b0, acc[nb][3] + b1);
    }
}

// ---------------- 4) CRF forward + gold score: warp per batch, reduction-free shift ----------------
__global__ void __launch_bounds__(32) k_crf(
    const int* __restrict__ labels,
    const float* __restrict__ trans,
    float* __restrict__ out)
{
    const int b = blockIdx.x;
    const int lane = threadIdx.x;
    __shared__ float ps[64];

    float eTc0[64], eTc1[64];
#pragma unroll 8
    for (int i = 0; i < 64; i++) {
        eTc0[i] = __expf(trans[i * 64 + lane]);
        eTc1[i] = __expf(trans[i * 64 + lane + 32]);
    }

    float d0 = g_emit[b][0][lane];
    float d1 = g_emit[b][0][lane + 32];
    float Cacc = 0.0f, Ckah = 0.0f;

    for (int t = 1; t < Ln; t++) {
        float c = __shfl_sync(0xffffffffu, d0, 0);
        ps[lane]      = __expf(d0 - c);
        ps[lane + 32] = __expf(d1 - c);
        __syncwarp();
        float s0a = 0.f, s0b = 0.f, s1a = 0.f, s1b = 0.f;
#pragma unroll
        for (int i = 0; i < 64; i += 2) {
            float pi = ps[i], pj = ps[i + 1];
            s0a = fmaf(pi, eTc0[i], s0a);
            s0b = fmaf(pj, eTc0[i + 1], s0b);
            s1a = fmaf(pi, eTc1[i], s1a);
            s1b = fmaf(pj, eTc1[i + 1], s1b);
        }
        d0 = g_emit[b][t][lane]      + __logf(s0a + s0b);
        d1 = g_emit[b][t][lane + 32] + __logf(s1a + s1b);
        float y = c - Ckah;
        float tt = Cacc + y;
        Ckah = (tt - Cacc) - y;
        Cacc = tt;
        __syncwarp();
    }

    float m = fmaxf(d0, d1);
#pragma unroll
    for (int o = 16; o > 0; o >>= 1)
        m = fmaxf(m, __shfl_xor_sync(0xffffffffu, m, o));
    float sp = __expf(d0 - m) + __expf(d1 - m);
#pragma unroll
    for (int o = 16; o > 0; o >>= 1)
        sp += __shfl_xor_sync(0xffffffffu, sp, o);
    float logz = m + __logf(sp) + Cacc;

    float gold = 0.0f;
    for (int t = lane; t < Ln; t += 32) {
        int lab = labels[b * Ln + t];
        gold += g_emit[b][t][lab];
        if (t < Ln - 1) {
            int lab2 = labels[b * Ln + t + 1];
            gold += trans[lab * 64 + lab2];
        }
    }
#pragma unroll
    for (int o = 16; o > 0; o >>= 1)
        gold += __shfl_xor_sync(0xffffffffu, gold, o);

    if (lane == 0) out[b] = logz - gold;
}

// ---------------- launch ----------------
extern "C" void kernel_launch(void* const* d_in, const int* in_sizes, int n_in,
                              void* d_out, int out_size)
{
    const float* x     = (const float*)d_in[0];
    const int*   lab   = (const int*)d_in[1];
    const float* wihf  = (const float*)d_in[2];
    const float* whhf  = (const float*)d_in[3];
    const float* bihf  = (const float*)d_in[4];
    const float* bhhf  = (const float*)d_in[5];
    const float* wihb  = (const float*)d_in[6];
    const float* whhb  = (const float*)d_in[7];
    const float* bihb  = (const float*)d_in[8];
    const float* bhhb  = (const float*)d_in[9];
    const float* wem   = (const float*)d_in[10];
    const float* bem   = (const float*)d_in[11];
    const float* trans = (const float*)d_in[12];
    float* out = (float*)d_out;

    k_cvt_x<<<16384, 256>>>(x);
    k_cvt_w<<<1088, 256>>>(wihf, wihb, wem);
    k_nop<<<1, 32>>>();                               // shifts ncu capture slot onto the GEMM
    dim3 gg(8, 512, 2);
    k_gemm_bf16<<<gg, 256>>>(bihf, bhhf, bihb, bhhb);
    k_lstm4<<<128, 256>>>(whhf, whhb);
    k_emit2<<<512, 256>>>(bem);
    k_crf<<<128, 32>>>(lab, trans, out);
}

// round 14
// speedup vs baseline: 3.4488x; 1.0753x over previous
#include <cuda_runtime.h>
#include <cstdint>

#define Bn 128
#define Ln 512
#define En 512
#define Hn 256
#define G4 1024
#define Kn 64

// ---------------- scratch (static device allocations) ----------------
__device__ uint32_t g_preB[2][Ln][Bn][G4/2];   // 268MB: pre-activations bf16x2 [dir][t][b][gate_pair]
__device__ uint32_t g_histB[Ln][Bn][Hn];       // 67MB: concat hidden states bf16x2 [t][b][h_pair]
__device__ float g_emit[Bn][Ln][Kn];           // emissions [b][t][k]
__device__ uint32_t g_xb[Bn][Ln][En/2];        // 67MB: x in bf16x2
__device__ uint32_t g_wihb2[2][G4][En/2];      // W_ih bf16x2 (2MB)
__device__ uint32_t g_wemb[Kn][En/2];          // w_emit bf16x2 (64KB)

__device__ __forceinline__ float sigf(float x) {
    return 1.0f / (1.0f + __expf(-x));
}
__device__ __forceinline__ float tanhfast(float x) {
    float e = __expf(2.0f * x);
    return 1.0f - __fdividef(2.0f, e + 1.0f);
}

__device__ __forceinline__ uint32_t pack_bf16(float lo, float hi) {
    uint32_t r;
    asm("cvt.rn.bf16x2.f32 %0, %1, %2;" : "=r"(r) : "f"(hi), "f"(lo));
    return r;
}
__device__ __forceinline__ float bflo(uint32_t w) { return __uint_as_float(w << 16); }
__device__ __forceinline__ float bfhi(uint32_t w) { return __uint_as_float(w & 0xffff0000u); }

__device__ __forceinline__ void mma_bf16(float* d, const uint32_t* a, const uint32_t* b) {
    asm volatile(
        "mma.sync.aligned.m16n8k16.row.col.f32.bf16.bf16.f32 "
        "{%0,%1,%2,%3}, {%4,%5,%6,%7}, {%8,%9}, {%0,%1,%2,%3};"
        : "+f"(d[0]), "+f"(d[1]), "+f"(d[2]), "+f"(d[3])
        : "r"(a[0]), "r"(a[1]), "r"(a[2]), "r"(a[3]), "r"(b[0]), "r"(b[1]));
}

__device__ __forceinline__ uint32_t smem_u32(const void* p) {
    uint32_t a;
    asm("{ .reg .u64 t; cvta.to.shared.u64 t, %1; cvt.u32.u64 %0, t; }" : "=r"(a) : "l"(p));
    return a;
}

#define LDSM4(d, a)                                                            \
    asm volatile("ldmatrix.sync.aligned.m8n8.x4.shared.b16 {%0,%1,%2,%3}, [%4];" \
        : "=r"((d)[0]), "=r"((d)[1]), "=r"((d)[2]), "=r"((d)[3]) : "r"(a))

// ---------------- 0) prep: fp32 -> bf16x2 conversions ----------------
__global__ void __launch_bounds__(256) k_cvt_x(const float* __restrict__ x) {
    uint32_t* dst = &g_xb[0][0][0];
    int i = blockIdx.x * 512 + threadIdx.x * 2;     // 2 float4 per thread
#pragma unroll
    for (int j = 0; j < 2; j++) {
        int f = i + j;
        float4 v = *(const float4*)(x + (size_t)f * 4);
        *(uint2*)(dst + (size_t)f * 2) = make_uint2(pack_bf16(v.x, v.y), pack_bf16(v.z, v.w));
    }
}

#define WF4 131072      // 1024*512/4
__global__ void __launch_bounds__(256) k_cvt_w(
    const float* __restrict__ wf, const float* __restrict__ wb,
    const float* __restrict__ wem)
{
    int f = blockIdx.x * 256 + threadIdx.x;          // float4 index
    const float* src;
    uint32_t* dst;
    if (f < WF4)           { src = wf;  dst = &g_wihb2[0][0][0]; }
    else if (f < 2 * WF4)  { src = wb;  dst = &g_wihb2[1][0][0]; f -= WF4; }
    else                   { src = wem; dst = &g_wemb[0][0];     f -= 2 * WF4;
                             if (f >= Kn * En / 4) return; }
    float4 v = *(const float4*)(src + (size_t)f * 4);
    *(uint2*)(dst + (size_t)f * 2) = make_uint2(pack_bf16(v.x, v.y), pack_bf16(v.z, v.w));
}

__global__ void k_nop() {}

// ---------------- 1) input GEMM (mma.sync bf16, ldmatrix + double buffer) ----------------
// C tile: M=128 batch x N=128 gates, K=512 in 16 stages of 32.
// SMEM layout [row][k2] with 20-word row stride (LDSM conflict-free: 80*m mod 128 spans
// 8 distinct 16B granules). Fragments via ldmatrix.x4; staging via STS.128.
#define RS 20
#define BUFW (128 * RS)

__global__ void __launch_bounds__(256) k_gemm_bf16(
    const float* __restrict__ bihf, const float* __restrict__ bhhf,
    const float* __restrict__ bihb, const float* __restrict__ bhhb)
{
    const int gtile = blockIdx.x;           // 0..7
    const int t     = blockIdx.y;           // 0..511
    const int dir   = blockIdx.z;           // 0,1
    const int t_eff = dir ? (Ln - 1 - t) : t;
    const int g0 = gtile * 128;

    __shared__ uint32_t As[2 * BUFW];       // x tile,  [buf][row b][k2] stride RS
    __shared__ uint32_t Bs[2 * BUFW];       // W tile,  [buf][row g][k2] stride RS

    const int tid  = threadIdx.x;
    const int wid  = tid >> 5;
    const int lane = tid & 31;
    const int wm   = (wid >> 2) * 64;   // warp M (batch) base
    const int wn   = (wid & 3) * 32;    // warp N (gate) base
    const int grp  = lane >> 2;         // 0..7
    const int qk   = lane & 3;          // 0..3

    // ldmatrix per-lane source coords
    const int lane15 = lane & 15;
    const int acol   = (lane & 16) ? 4 : 0;                 // A: matrices 2,3 take k2+4
    const int brow0  = wn + ((lane & 16) >> 1) + (lane & 7);// B pair0: ni = lane>>4
    const int bcol   = (lane & 8) ? 4 : 0;                  // B: odd 8-lane groups take k2+4

    const uint32_t baseA = smem_u32(As);
    const uint32_t baseB = smem_u32(Bs);
    uint32_t aoff[4];
#pragma unroll
    for (int mi = 0; mi < 4; mi++)
        aoff[mi] = (uint32_t)((wm + mi * 16 + lane15) * RS + acol);
    const uint32_t boff0 = (uint32_t)(brow0 * RS + bcol);
    const uint32_t boff1 = boff0 + 16 * RS;

    // staging coords: thread -> rows r0,r1 (quad q of 4 words)
    const int r0 = tid >> 2;            // 0..63
    const int r1 = r0 + 64;             // 64..127
    const int q  = tid & 3;
    const uint32_t* __restrict__ xa0 = &g_xb[r0][t_eff][q * 4];
    const uint32_t* __restrict__ xa1 = &g_xb[r1][t_eff][q * 4];
    const uint32_t* __restrict__ wa0 = &g_wihb2[dir][g0 + r0][q * 4];
    const uint32_t* __restrict__ wa1 = &g_wihb2[dir][g0 + r1][q * 4];

    uint4 va0, va1, vb0, vb1;
#define LOADG(s) do {                                      \
        va0 = *(const uint4*)(xa0 + (s) * 16);             \
        va1 = *(const uint4*)(xa1 + (s) * 16);             \
        vb0 = *(const uint4*)(wa0 + (s) * 16);             \
        vb1 = *(const uint4*)(wa1 + (s) * 16);             \
    } while (0)
#define STOREG(bu) do {                                                \
        *(uint4*)(As + (bu) * BUFW + r0 * RS + q * 4) = va0;           \
        *(uint4*)(As + (bu) * BUFW + r1 * RS + q * 4) = va1;           \
        *(uint4*)(Bs + (bu) * BUFW + r0 * RS + q * 4) = vb0;           \
        *(uint4*)(Bs + (bu) * BUFW + r1 * RS + q * 4) = vb1;           \
    } while (0)

    float acc[4][4][4];                 // [mi][ni][reg]
#pragma unroll
    for (int mi = 0; mi < 4; mi++)
#pragma unroll
        for (int ni = 0; ni < 4; ni++)
#pragma unroll
            for (int r = 0; r < 4; r++) acc[mi][ni][r] = 0.0f;

    LOADG(0);
    STOREG(0);
    __syncthreads();

    for (int s = 0; s < 16; s++) {
        const uint32_t curw = (uint32_t)(s & 1) * BUFW;
        if (s < 15) LOADG(s + 1);       // overlap next-stage LDG with this stage's mma

#pragma unroll
        for (int kc2 = 0; kc2 < 16; kc2 += 8) {
            uint32_t af[4][4];
#pragma unroll
            for (int mi = 0; mi < 4; mi++)
                LDSM4(af[mi], baseA + (curw + aoff[mi] + kc2) * 4);
            uint32_t bt0[4], bt1[4];
            LDSM4(bt0, baseB + (curw + boff0 + kc2) * 4);
            LDSM4(bt1, baseB + (curw + boff1 + kc2) * 4);
#pragma unroll
            for (int mi = 0; mi < 4; mi++) {
                mma_bf16(acc[mi][0], af[mi], bt0);
                mma_bf16(acc[mi][1], af[mi], bt0 + 2);
                mma_bf16(acc[mi][2], af[mi], bt1);
                mma_bf16(acc[mi][3], af[mi], bt1 + 2);
            }
        }

        if (s < 15) {
            STOREG((s + 1) & 1);
            __syncthreads();
        }
    }
#undef LOADG
#undef STOREG

    // epilogue
    const float* __restrict__ bih = dir ? bihb : bihf;
    const float* __restrict__ bhh = dir ? bhhb : bhhf;
#pragma unroll
    for (int ni = 0; ni < 4; ni++) {
        int gate0 = g0 + wn + ni * 8 + 2 * qk;
        float bias0 = bih[gate0] + bhh[gate0];
        float bias1 = bih[gate0 + 1] + bhh[gate0 + 1];
        int g2w = (g0 + wn + ni * 8) / 2 + qk;
#pragma unroll
        for (int mi = 0; mi < 4; mi++) {
            int bA = wm + mi * 16 + grp;
            g_preB[dir][t][bA][g2w]     = pack_bf16(acc[mi][ni][0] + bias0, acc[mi][ni][1] + bias1);
            g_preB[dir][t][bA + 8][g2w] = pack_bf16(acc[mi][ni][2] + bias0, acc[mi][ni][3] + bias1);
        }
    }
}

// ---------------- 2) LSTM recurrence: 8-CTA cluster, DSMEM h-exchange, split acc chains ----------------
__global__ void __launch_bounds__(256) __cluster_dims__(8, 1, 1) k_lstm4(
    const float* __restrict__ whf, const float* __restrict__ whb)
{
    const int dir  = blockIdx.x >> 6;
    const int sub  = blockIdx.x & 63;
    const int bblk = sub >> 3;
    const int gs   = sub & 7;                // == cluster rank
    const float* __restrict__ whh = dir ? whb : whf;

    const int tid  = threadIdx.x;
    const int wid  = tid >> 5;
    const int lane = tid & 31;
    const int grp  = lane >> 2;
    const int qk   = lane & 3;
    const int bm   = bblk * 16;              // CTA batch base
    const int m0w  = gs * 32 + wid * 4;      // warp's 4 hidden units

    // h staging, double-buffered: [parity][k2 row 0..127][b col 0..15], stride 24 (conflict-free reads)
    __shared__ uint32_t hsm[2][128 * 24];    // 24.6 KB

    // ---- B fragments (W_hh slice for this warp), persistent in registers ----
    uint32_t B0[2][16], B1[2][16];
#pragma unroll
    for (int nt = 0; nt < 2; nt++) {
        int c = nt * 8 + grp;                          // warp col 0..15
        int gcol = (c >> 2) * 256 + m0w + (c & 3);     // global gate
        const float* wr = whh + (size_t)gcol * Hn;
#pragma unroll
        for (int kb = 0; kb < 16; kb++) {
            float2 w0 = *(const float2*)(wr + kb * 16 + 2 * qk);
            float2 w1 = *(const float2*)(wr + kb * 16 + 8 + 2 * qk);
            B0[nt][kb] = pack_bf16(w0.x, w0.y);
            B1[nt][kb] = pack_bf16(w1.x, w1.y);
        }
    }

    float cst0 = 0.0f, cst1 = 0.0f;                   // cell state (2 per lane)
    const int rb      = (qk >= 2) ? 2 : 0;
    const int b_loc   = grp + ((qk >= 2) ? 8 : 0);    // local batch col 0..15
    const int b_row   = bm + b_loc;
    const int m2w     = gs * 16 + wid * 2 + (qk & 1); // global k2 row 0..127
    const int hwrd    = dir * 128 + m2w;              // hist word col

    const int wrd0 = ((qk >> 1)) * 128 + m2w;       // nt=0 preB word
    const int wrd1 = (2 + (qk >> 1)) * 128 + m2w;   // nt=1 preB word

    const uint32_t ha0 = smem_u32(&hsm[0][m2w * 24 + b_loc]);
    const uint32_t ha1 = smem_u32(&hsm[1][m2w * 24 + b_loc]);

    // prefetch preB for t=0
    uint32_t pw[4];
    pw[0] = g_preB[dir][0][bm + grp][wrd0];
    pw[1] = g_preB[dir][0][bm + grp + 8][wrd0];
    pw[2] = g_preB[dir][0][bm + grp][wrd1];
    pw[3] = g_preB[dir][0][bm + grp + 8][wrd1];

    for (int t = 0; t < Ln; t++) {
        float acc[2][4], acd[2][4];      // even-kb and odd-kb accumulator chains
#pragma unroll
        for (int nt = 0; nt < 2; nt++)
#pragma unroll
            for (int r = 0; r < 4; r++) { acc[nt][r] = 0.0f; acd[nt][r] = 0.0f; }

        if (t > 0) {
            const uint32_t* __restrict__ hb = &hsm[(t - 1) & 1][0];
#pragma unroll
            for (int kb = 0; kb < 16; kb++) {
                uint32_t a[4];
                const int r0 = (kb * 8 + qk) * 24;
                a[0] = hb[r0 + grp];
                a[1] = hb[r0 + grp + 8];
                a[2] = hb[r0 + 96 + grp];        // +4 rows
                a[3] = hb[r0 + 96 + grp + 8];
                uint32_t b0[2] = {B0[0][kb], B1[0][kb]};
                uint32_t b1[2] = {B0[1][kb], B1[1][kb]};
                float* d0 = (kb & 1) ? acd[0] : acc[0];
                float* d1 = (kb & 1) ? acd[1] : acc[1];
                mma_bf16(d0, a, b0);
                mma_bf16(d1, a, b1);
            }
#pragma unroll
            for (int nt = 0; nt < 2; nt++)
#pragma unroll
                for (int r = 0; r < 4; r++) acc[nt][r] += acd[nt][r];
        }

        // add pre-activations (prefetched)
        acc[0][0] += bflo(pw[0]); acc[0][1] += bfhi(pw[0]);
        acc[0][2] += bflo(pw[1]); acc[0][3] += bfhi(pw[1]);
        acc[1][0] += bflo(pw[2]); acc[1][1] += bfhi(pw[2]);
        acc[1][2] += bflo(pw[3]); acc[1][3] += bfhi(pw[3]);

        // exchange with lane^2: (i,g) <-> (f,o)
        float recv[2][4];
#pragma unroll
        for (int nt = 0; nt < 2; nt++)
#pragma unroll
            for (int r = 0; r < 4; r++)
                recv[nt][r] = __shfl_xor_sync(0xffffffffu, acc[nt][r], 2);

        const bool ig = (qk < 2);
        float h0, h1;
        {
            float i_ = ig ? acc[0][rb + 0] : recv[0][rb + 0];
            float f_ = ig ? recv[0][rb + 0] : acc[0][rb + 0];
            float g_ = ig ? acc[1][rb + 0] : recv[1][rb + 0];
            float o_ = ig ? recv[1][rb + 0] : acc[1][rb + 0];
            cst0 = sigf(f_) * cst0 + sigf(i_) * tanhfast(g_);
            h0 = sigf(o_) * tanhfast(cst0);
        }
        {
            float i_ = ig ? acc[0][rb + 1] : recv[0][rb + 1];
            float f_ = ig ? recv[0][rb + 1] : acc[0][rb + 1];
            float g_ = ig ? acc[1][rb + 1] : recv[1][rb + 1];
            float o_ = ig ? recv[1][rb + 1] : acc[1][rb + 1];
            cst1 = sigf(f_) * cst1 + sigf(i_) * tanhfast(g_);
            h1 = sigf(o_) * tanhfast(cst1);
        }

        const uint32_t hw = pack_bf16(h0, h1);
        const int rt = dir ? (Ln - 1 - t) : t;
        __stcg(&g_histB[rt][b_row][hwrd], hw);

        if (t != Ln - 1) {
            // multicast h word to all 8 cluster CTAs (skipped on the last step: dead +
            // would race peer CTA exit)
            const uint32_t laddr = (t & 1) ? ha1 : ha0;
#pragma unroll
            for (int r = 0; r < 8; r++) {
                uint32_t raddr;
                asm("mapa.shared::cluster.u32 %0, %1, %2;" : "=r"(raddr) : "r"(laddr), "r"(r));
                asm volatile("st.shared::cluster.u32 [%0], %1;" :: "r"(raddr), "r"(hw) : "memory");
            }
            // prefetch next step's preB before the barrier (no dependency)
            pw[0] = __ldcg(&g_preB[dir][t + 1][bm + grp][wrd0]);
            pw[1] = __ldcg(&g_preB[dir][t + 1][bm + grp + 8][wrd0]);
            pw[2] = __ldcg(&g_preB[dir][t + 1][bm + grp][wrd1]);
            pw[3] = __ldcg(&g_preB[dir][t + 1][bm + grp + 8][wrd1]);
            asm volatile("barrier.cluster.arrive.aligned;" ::: "memory");
            asm volatile("barrier.cluster.wait.aligned;" ::: "memory");
        }
    }

    // trailing cluster barrier: no CTA exits while any peer's remote traffic could be in flight
    asm volatile("barrier.cluster.arrive.aligned;" ::: "memory");
    asm volatile("barrier.cluster.wait.aligned;" ::: "memory");
}

// ---------------- 3) emit GEMM (mma bf16): emit[b][t][k] = histB[t][b] @ wemb^T + b_emit ----------------
__global__ void __launch_bounds__(256) k_emit2(const float* __restrict__ bem)
{
    const int t = blockIdx.x;
    __shared__ uint32_t As2[32][136];   // [k2][b]
    __shared__ uint32_t Bs2[32][72];    // [k2][k-col]

    const int tid  = threadIdx.x;
    const int wid  = tid >> 5;
    const int lane = tid & 31;
    const int grp  = lane >> 2;
    const int qk   = lane & 3;
    const int wm   = wid * 16;          // warp batch base

    float acc[8][4];
#pragma unroll
    for (int nb = 0; nb < 8; nb++)
#pragma unroll
        for (int r = 0; r < 4; r++) acc[nb][r] = 0.0f;

    for (int c = 0; c < 8; c++) {                  // K chunks: 64 h (32 words)
        const int k0w = c * 32;
#pragma unroll
        for (int i = 0; i < 4; i++) {              // A: 128 rows x 32 words
            int idx = (i << 8) + tid;
            int r   = idx >> 3;                    // 0..127
            int q   = idx & 7;
            uint4 v = *(const uint4*)&g_histB[t][r][k0w + q * 4];
            As2[q * 4 + 0][r] = v.x; As2[q * 4 + 1][r] = v.y;
            As2[q * 4 + 2][r] = v.z; As2[q * 4 + 3][r] = v.w;
        }
#pragma unroll
        for (int i = 0; i < 2; i++) {              // B: 64 rows x 32 words
            int idx = (i << 8) + tid;
            int r   = idx >> 3;                    // 0..63
            int q   = idx & 7;
            uint4 v = *(const uint4*)&g_wemb[r][k0w + q * 4];
            Bs2[q * 4 + 0][r] = v.x; Bs2[q * 4 + 1][r] = v.y;
            Bs2[q * 4 + 2][r] = v.z; Bs2[q * 4 + 3][r] = v.w;
        }
        __syncthreads();
#pragma unroll
        for (int kb = 0; kb < 4; kb++) {
            int k2 = kb * 8;
            uint32_t a[4];
            a[0] = As2[k2 + qk][wm + grp];
            a[1] = As2[k2 + qk][wm + grp + 8];
            a[2] = As2[k2 + 4 + qk][wm + grp];
            a[3] = As2[k2 + 4 + qk][wm + grp + 8];
#pragma unroll
            for (int nb = 0; nb < 8; nb++) {
                uint32_t b[2] = {Bs2[k2 + qk][nb * 8 + grp], Bs2[k2 + 4 + qk][nb * 8 + grp]};
                mma_bf16(acc[nb], a, b);
            }
        }
        __syncthreads();
    }

#pragma unroll
    for (int nb = 0; nb < 8; nb++) {
        int k = nb * 8 + qk * 2;
        float b0 = bem[k], b1 = bem[k + 1];
        *(float2*)&g_emit[wm + grp][t][k]     = make_float2(acc[nb][0] + b0, acc[nb][1] + b1);
        *(float2*)&g_emit[wm + grp + 8][t][k] = make_float2(acc[nb][2] + b0, acc[nb][3] + b1);
    }
}

// ---------------- 4) CRF forward + gold score: warp per batch, reduction-free shift ----------------
__global__ void __launch_bounds__(32) k_crf(
    const int* __restrict__ labels,
    const float* __restrict__ trans,
    float* __restrict__ out)
{
    const int b = blockIdx.x;
    const int lane = threadIdx.x;
    __shared__ float ps[64];

    float eTc0[64], eTc1[64];
#pragma unroll 8
    for (int i = 0; i < 64; i++) {
        eTc0[i] = __expf(trans[i * 64 + lane]);
        eTc1[i] = __expf(trans[i * 64 + lane + 32]);
    }

    float d0 = g_emit[b][0][lane];
    float d1 = g_emit[b][0][lane + 32];
    float Cacc = 0.0f, Ckah = 0.0f;

    for (int t = 1; t < Ln; t++) {
        float c = __shfl_sync(0xffffffffu, d0, 0);
        ps[lane]      = __expf(d0 - c);
        ps[lane + 32] = __expf(d1 - c);
        __syncwarp();
        float s0a = 0.f, s0b = 0.f, s1a = 0.f, s1b = 0.f;
#pragma unroll
        for (int i = 0; i < 64; i += 2) {
            float pi = ps[i], pj = ps[i + 1];
            s0a = fmaf(pi, eTc0[i], s0a);
            s0b = fmaf(pj, eTc0[i + 1], s0b);
            s1a = fmaf(pi, eTc1[i], s1a);
            s1b = fmaf(pj, eTc1[i + 1], s1b);
        }
        d0 = g_emit[b][t][lane]      + __logf(s0a + s0b);
        d1 = g_emit[b][t][lane + 32] + __logf(s1a + s1b);
        float y = c - Ckah;
        float tt = Cacc + y;
        Ckah = (tt - Cacc) - y;
        Cacc = tt;
        __syncwarp();
    }

    float m = fmaxf(d0, d1);
#pragma unroll
    for (int o = 16; o > 0; o >>= 1)
        m = fmaxf(m, __shfl_xor_sync(0xffffffffu, m, o));
    float sp = __expf(d0 - m) + __expf(d1 - m);
#pragma unroll
    for (int o = 16; o > 0; o >>= 1)
        sp += __shfl_xor_sync(0xffffffffu, sp, o);
    float logz = m + __logf(sp) + Cacc;

    float gold = 0.0f;
    for (int t = lane; t < Ln; t += 32) {
        int lab = labels[b * Ln + t];
        gold += g_emit[b][t][lab];
        if (t < Ln - 1) {
            int lab2 = labels[b * Ln + t + 1];
            gold += trans[lab * 64 + lab2];
        }
    }
#pragma unroll
    for (int o = 16; o > 0; o >>= 1)
        gold += __shfl_xor_sync(0xffffffffu, gold, o);

    if (lane == 0) out[b] = logz - gold;
}

// ---------------- launch ----------------
extern "C" void kernel_launch(void* const* d_in, const int* in_sizes, int n_in,
                              void* d_out, int out_size)
{
    const float* x     = (const float*)d_in[0];
    const int*   lab   = (const int*)d_in[1];
    const float* wihf  = (const float*)d_in[2];
    const float* whhf  = (const float*)d_in[3];
    const float* bihf  = (const float*)d_in[4];
    const float* bhhf  = (const float*)d_in[5];
    const float* wihb  = (const float*)d_in[6];
    const float* whhb  = (const float*)d_in[7];
    const float* bihb  = (const float*)d_in[8];
    const float* bhhb  = (const float*)d_in[9];
    const float* wem   = (const float*)d_in[10];
    const float* bem   = (const float*)d_in[11];
    const float* trans = (const float*)d_in[12];
    float* out = (float*)d_out;

    k_cvt_x<<<16384, 256>>>(x);
    k_cvt_w<<<1088, 256>>>(wihf, wihb, wem);
    k_nop<<<1, 32>>>();                               // keeps ncu capture slot on the GEMM
    dim3 gg(8, 512, 2);
    k_gemm_bf16<<<gg, 256>>>(bihf, bhhf, bihb, bhhb);
    k_lstm4<<<128, 256>>>(whhf, whhb);
    k_emit2<<<512, 256>>>(bem);
    k_crf<<<128, 32>>>(lab, trans, out);
}